// round 2
// baseline (speedup 1.0000x reference)
#include <cuda_runtime.h>
#include <cuda_bf16.h>
#include <stdint.h>

#define NB    4
#define NPTS  16384
#define NCTR  1024
#define NSAMP 32
#define R2    0.04f

// ---------------- scratch (no allocations allowed) ----------------
__device__ float g_featsT[(size_t)NB * NPTS * 64];   // (B,N,C)
__device__ int   g_ballidx[NB * NCTR * NSAMP];

// ---------------------------------------------------------------------------
// 1) transpose features (B,64,N) -> (B,N,64)
// ---------------------------------------------------------------------------
__global__ void transpose_kernel(const float* __restrict__ f)
{
    __shared__ float tile[32][33];
    int n0 = blockIdx.x * 32, c0 = blockIdx.y * 32, b = blockIdx.z;
    int tx = threadIdx.x, ty = threadIdx.y;
    const float* src = f + (size_t)b * 64 * NPTS;
#pragma unroll
    for (int r = 0; r < 32; r += 8)
        tile[ty + r][tx] = src[(size_t)(c0 + ty + r) * NPTS + n0 + tx];
    __syncthreads();
    float* dst = g_featsT + (size_t)b * NPTS * 64;
#pragma unroll
    for (int r = 0; r < 32; r += 8)
        dst[(size_t)(n0 + ty + r) * 64 + c0 + tx] = tile[tx][ty + r];
}

// ---------------------------------------------------------------------------
// 2) furthest point sampling: 1 block/batch, 1024 threads, exact arithmetic.
//    Writes new_xyz into d_out[0 .. 12288).
// ---------------------------------------------------------------------------
__global__ void __launch_bounds__(1024, 1)
fps_kernel(const float* __restrict__ xyz, float* __restrict__ out)
{
    extern __shared__ float sm[];
    float* shx = sm;
    float* shy = sm + NPTS;
    float* shz = sm + 2 * NPTS;
    __shared__ unsigned long long warpkey[32];
    __shared__ unsigned int s_win;

    const int b = blockIdx.x, tid = threadIdx.x;
    const float* xb = xyz + (size_t)b * NPTS * 3;

    for (int p = tid; p < NPTS; p += 1024) {
        float x = xb[3 * p], y = xb[3 * p + 1], z = xb[3 * p + 2];
        shx[p] = x; shy[p] = y; shz[p] = z;
    }
    float dist[16];
#pragma unroll
    for (int j = 0; j < 16; j++) dist[j] = 10000000000.0f;
    __syncthreads();

    unsigned win = 0;
    float* outx = out + (size_t)b * NCTR * 3;

    for (int k = 0; k < NCTR; ++k) {
        if (tid == 0) {
            outx[3 * k]     = shx[win];
            outx[3 * k + 1] = shy[win];
            outx[3 * k + 2] = shz[win];
        }
        if (k == NCTR - 1) break;

        float cx = shx[win], cy = shy[win], cz = shz[win];
        float bestv = -1.0f;
        unsigned besti = 0;
#pragma unroll
        for (int j = 0; j < 4; ++j) {
            int q = j * 1024 + tid;           // float4 index
            float4 xv = ((const float4*)shx)[q];
            float4 yv = ((const float4*)shy)[q];
            float4 zv = ((const float4*)shz)[q];
            float dx, dy, dz, d0, d1, d2, d3;
            dx = __fsub_rn(xv.x, cx); dy = __fsub_rn(yv.x, cy); dz = __fsub_rn(zv.x, cz);
            d0 = __fadd_rn(__fadd_rn(__fmul_rn(dx, dx), __fmul_rn(dy, dy)), __fmul_rn(dz, dz));
            dx = __fsub_rn(xv.y, cx); dy = __fsub_rn(yv.y, cy); dz = __fsub_rn(zv.y, cz);
            d1 = __fadd_rn(__fadd_rn(__fmul_rn(dx, dx), __fmul_rn(dy, dy)), __fmul_rn(dz, dz));
            dx = __fsub_rn(xv.z, cx); dy = __fsub_rn(yv.z, cy); dz = __fsub_rn(zv.z, cz);
            d2 = __fadd_rn(__fadd_rn(__fmul_rn(dx, dx), __fmul_rn(dy, dy)), __fmul_rn(dz, dz));
            dx = __fsub_rn(xv.w, cx); dy = __fsub_rn(yv.w, cy); dz = __fsub_rn(zv.w, cz);
            d3 = __fadd_rn(__fadd_rn(__fmul_rn(dx, dx), __fmul_rn(dy, dy)), __fmul_rn(dz, dz));

            int r = j * 4;
            float n0 = fminf(dist[r],     d0);
            float n1 = fminf(dist[r + 1], d1);
            float n2 = fminf(dist[r + 2], d2);
            float n3 = fminf(dist[r + 3], d3);
            dist[r] = n0; dist[r + 1] = n1; dist[r + 2] = n2; dist[r + 3] = n3;
            unsigned base = 4u * (unsigned)q;
            if (n0 > bestv) { bestv = n0; besti = base; }
            if (n1 > bestv) { bestv = n1; besti = base + 1; }
            if (n2 > bestv) { bestv = n2; besti = base + 2; }
            if (n3 > bestv) { bestv = n3; besti = base + 3; }
        }
        unsigned long long key =
            ((unsigned long long)__float_as_uint(bestv) << 32) | (unsigned)(~besti);
#pragma unroll
        for (int o = 16; o; o >>= 1) {
            unsigned long long other = __shfl_down_sync(0xffffffffu, key, o);
            if (other > key) key = other;
        }
        if ((tid & 31) == 0) warpkey[tid >> 5] = key;
        __syncthreads();
        if (tid < 32) {
            unsigned long long k2 = warpkey[tid];
#pragma unroll
            for (int o = 16; o; o >>= 1) {
                unsigned long long other = __shfl_down_sync(0xffffffffu, k2, o);
                if (other > k2) k2 = other;
            }
            if (tid == 0) s_win = ~(unsigned)k2;
        }
        __syncthreads();
        win = s_win;
    }
}

// ---------------------------------------------------------------------------
// 3) ball query: 1 warp per center, ascending-index append with early exit.
// ---------------------------------------------------------------------------
__global__ void __launch_bounds__(256)
ballquery_kernel(const float* __restrict__ xyz, const float* __restrict__ out)
{
    int gw = (blockIdx.x * blockDim.x + threadIdx.x) >> 5;
    int lane = threadIdx.x & 31;
    if (gw >= NB * NCTR) return;
    int b = gw >> 10, j = gw & (NCTR - 1);

    const float* xb = xyz + (size_t)b * NPTS * 3;
    const float* cp = out + ((size_t)b * NCTR + j) * 3;
    float cx = cp[0], cy = cp[1], cz = cp[2];
    int* outi = g_ballidx + ((size_t)b * NCTR + j) * NSAMP;

    int cnt = 0;
    int firstidx = 0;
    for (int c = 0; c < NPTS / 32 && cnt < NSAMP; ++c) {
        int p = c * 32 + lane;
        float x = xb[3 * p], y = xb[3 * p + 1], z = xb[3 * p + 2];
        float dx = __fsub_rn(cx, x), dy = __fsub_rn(cy, y), dz = __fsub_rn(cz, z);
        float d2 = __fadd_rn(__fadd_rn(__fmul_rn(dx, dx), __fmul_rn(dy, dy)),
                             __fmul_rn(dz, dz));
        bool in = d2 < R2;
        unsigned m = __ballot_sync(0xffffffffu, in);
        if (m) {
            if (cnt == 0) {
                int src = __ffs(m) - 1;
                firstidx = __shfl_sync(0xffffffffu, p, src);
            }
            int rank = cnt + __popc(m & ((1u << lane) - 1u));
            if (in && rank < NSAMP) outi[rank] = p;
            cnt += __popc(m);
        }
    }
    if (cnt < NSAMP && lane >= cnt) outi[lane] = firstidx;  // pad with first
}

// ---------------------------------------------------------------------------
// 4) gather + MLP(67->64->64->128) + maxpool. 128 threads, 4 centers/block.
// ---------------------------------------------------------------------------
#define BUFW 68
#define SM_W1   0
#define SM_W2   (SM_W1 + 67 * 64)
#define SM_W3   (SM_W2 + 64 * 64)
#define SM_BUFA (SM_W3 + 64 * 128)
#define SM_BUFB (SM_BUFA + 32 * BUFW)
#define SM_SV   (SM_BUFB + 32 * BUFW)
#define SM_FLOATS (SM_SV + 512)
#define SMEM_MLP_BYTES (SM_FLOATS * 4 + (128 + 32) * 4)

__global__ void __launch_bounds__(128, 2)
mlp_kernel(const float* __restrict__ xyz,
           const float* __restrict__ W1, const float* __restrict__ s1, const float* __restrict__ b1,
           const float* __restrict__ W2, const float* __restrict__ s2, const float* __restrict__ b2,
           const float* __restrict__ W3, const float* __restrict__ s3, const float* __restrict__ b3,
           float* __restrict__ out)
{
    extern __shared__ float smem[];
    float* W1s  = smem + SM_W1;     // [i][o] 67x64
    float* W2s  = smem + SM_W2;     // [i][o] 64x64
    float* W3s  = smem + SM_W3;     // [i][o] 64x128
    float* bufA = smem + SM_BUFA;   // [32][68]
    float* bufB = smem + SM_BUFB;   // [32][68]
    float* sv   = smem + SM_SV;     // s1 b1 s2 b2 s3 b3
    int*  pooled = (int*)(smem + SM_FLOATS);
    int*  sidx   = pooled + 128;

    int t = threadIdx.x;
    for (int e = t; e < 64 * 67; e += 128) { int o = e / 67, i = e % 67; W1s[i * 64 + o] = W1[e]; }
    for (int e = t; e < 64 * 64; e += 128) { int o = e >> 6, i = e & 63; W2s[i * 64 + o] = W2[e]; }
    for (int e = t; e < 128 * 64; e += 128){ int o = e >> 6, i = e & 63; W3s[i * 128 + o] = W3[e]; }
    if (t < 64) { sv[t] = s1[t]; sv[64 + t] = b1[t]; sv[128 + t] = s2[t]; sv[192 + t] = b2[t]; }
    sv[256 + t] = s3[t];
    sv[384 + t] = b3[t];

    int s = t >> 2, q = t & 3;

    for (int c = 0; c < 4; ++c) {
        int cid = blockIdx.x * 4 + c;
        int b = cid >> 10, j = cid & (NCTR - 1);

        pooled[t] = 0;
        if (t < 32) sidx[t] = g_ballidx[(size_t)cid * NSAMP + t];
        __syncthreads();

        const float* cp = out + ((size_t)b * NCTR + j) * 3;
        float cx = cp[0], cy = cp[1], cz = cp[2];
        {
            int pi = sidx[s];
            const float* frow = g_featsT + ((size_t)b * NPTS + pi) * 64;
            if (q == 0) {
                const float* pr = xyz + ((size_t)b * NPTS + pi) * 3;
                bufA[s * BUFW + 0] = pr[0] - cx;
                bufA[s * BUFW + 1] = pr[1] - cy;
                bufA[s * BUFW + 2] = pr[2] - cz;
            }
#pragma unroll
            for (int k2 = 0; k2 < 16; ++k2)
                bufA[s * BUFW + 3 + q * 16 + k2] = frow[q * 16 + k2];
        }
        __syncthreads();

        // Layer 1: 67 -> 64
        {
            float acc[16];
#pragma unroll
            for (int k2 = 0; k2 < 16; ++k2) acc[k2] = 0.0f;
            const float* gin = bufA + s * BUFW;
            for (int i = 0; i < 67; ++i) {
                float gv = gin[i];
                const float* wr = W1s + i * 64 + q * 16;
#pragma unroll
                for (int k2 = 0; k2 < 16; ++k2) acc[k2] = fmaf(wr[k2], gv, acc[k2]);
            }
#pragma unroll
            for (int k2 = 0; k2 < 16; ++k2) {
                int o = q * 16 + k2;
                bufB[s * BUFW + o] = fmaxf(fmaf(acc[k2], sv[o], sv[64 + o]), 0.0f);
            }
        }
        __syncthreads();

        // Layer 2: 64 -> 64
        {
            float acc[16];
#pragma unroll
            for (int k2 = 0; k2 < 16; ++k2) acc[k2] = 0.0f;
            const float* gin = bufB + s * BUFW;
            for (int i = 0; i < 64; ++i) {
                float gv = gin[i];
                const float* wr = W2s + i * 64 + q * 16;
#pragma unroll
                for (int k2 = 0; k2 < 16; ++k2) acc[k2] = fmaf(wr[k2], gv, acc[k2]);
            }
#pragma unroll
            for (int k2 = 0; k2 < 16; ++k2) {
                int o = q * 16 + k2;
                bufA[s * BUFW + o] = fmaxf(fmaf(acc[k2], sv[128 + o], sv[192 + o]), 0.0f);
            }
        }
        __syncthreads();

        // Layer 3: 64 -> 128 + maxpool
        {
            float acc[32];
#pragma unroll
            for (int k2 = 0; k2 < 32; ++k2) acc[k2] = 0.0f;
            const float* gin = bufA + s * BUFW;
            for (int i = 0; i < 64; ++i) {
                float gv = gin[i];
                const float* wr = W3s + i * 128 + q * 32;
#pragma unroll
                for (int k2 = 0; k2 < 32; ++k2) acc[k2] = fmaf(wr[k2], gv, acc[k2]);
            }
#pragma unroll
            for (int k2 = 0; k2 < 32; ++k2) {
                int o = q * 32 + k2;
                float y = fmaxf(fmaf(acc[k2], sv[256 + o], sv[384 + o]), 0.0f);
                atomicMax(&pooled[o], __float_as_int(y));
            }
        }
        __syncthreads();

        out[12288 + ((size_t)b * 128 + t) * NCTR + j] = __int_as_float(pooled[t]);
        __syncthreads();
    }
}

// ---------------------------------------------------------------------------
extern "C" void kernel_launch(void* const* d_in, const int* in_sizes, int n_in,
                              void* d_out, int out_size)
{
    const float* xyz      = (const float*)d_in[0];
    const float* features = (const float*)d_in[1];
    const float* W1 = (const float*)d_in[2];
    const float* s1 = (const float*)d_in[3];
    const float* b1 = (const float*)d_in[4];
    const float* W2 = (const float*)d_in[5];
    const float* s2 = (const float*)d_in[6];
    const float* b2 = (const float*)d_in[7];
    const float* W3 = (const float*)d_in[8];
    const float* s3 = (const float*)d_in[9];
    const float* b3 = (const float*)d_in[10];
    float* out = (float*)d_out;

    cudaFuncSetAttribute(fps_kernel, cudaFuncAttributeMaxDynamicSharedMemorySize,
                         NPTS * 3 * sizeof(float));
    cudaFuncSetAttribute(mlp_kernel, cudaFuncAttributeMaxDynamicSharedMemorySize,
                         SMEM_MLP_BYTES);

    transpose_kernel<<<dim3(NPTS / 32, 2, NB), dim3(32, 8)>>>(features);
    fps_kernel<<<NB, 1024, NPTS * 3 * sizeof(float)>>>(xyz, out);
    ballquery_kernel<<<(NB * NCTR * 32) / 256, 256>>>(xyz, out);
    mlp_kernel<<<(NB * NCTR) / 4, 128, SMEM_MLP_BYTES>>>(
        xyz, W1, s1, b1, W2, s2, b2, W3, s3, b3, out);
}

// round 4
// speedup vs baseline: 1.6750x; 1.6750x over previous
#include <cuda_runtime.h>
#include <cuda_bf16.h>
#include <stdint.h>

#define NB    4
#define NPTS  16384
#define NCTR  1024
#define NSAMP 32
#define R2    0.04f
#define FPSC  4              // FPS cluster size (CTAs per batch)
#define PPC   (NPTS / FPSC)  // points per CTA = 4096

// ---------------- scratch (no allocations allowed) ----------------
__device__ float g_featsT[(size_t)NB * NPTS * 64];   // (B,N,C)
__device__ int   g_ballidx[NB * NCTR * NSAMP];

// ---------------- small PTX helpers ----------------
__device__ __forceinline__ uint32_t smem_u32(const void* p) {
    uint32_t a;
    asm("{ .reg .u64 t; cvta.to.shared.u64 t, %1; cvt.u32.u64 %0, t; }"
        : "=r"(a) : "l"(p));
    return a;
}
__device__ __forceinline__ uint32_t mapa32(uint32_t a, uint32_t r) {
    uint32_t o;
    asm("mapa.shared::cluster.u32 %0, %1, %2;" : "=r"(o) : "r"(a), "r"(r));
    return o;
}
__device__ __forceinline__ void st_cluster_b64(uint32_t a, unsigned long long v) {
    asm volatile("st.shared::cluster.b64 [%0], %1;" :: "r"(a), "l"(v) : "memory");
}
__device__ __forceinline__ void st_cluster_b32(uint32_t a, uint32_t v) {
    asm volatile("st.shared::cluster.b32 [%0], %1;" :: "r"(a), "r"(v) : "memory");
}
#define CLUSTER_SYNC() do { \
    asm volatile("barrier.cluster.arrive.aligned;" ::: "memory"); \
    asm volatile("barrier.cluster.wait.aligned;" ::: "memory"); } while (0)

// ---------------------------------------------------------------------------
// 1) transpose features (B,64,N) -> (B,N,64)
// ---------------------------------------------------------------------------
__global__ void transpose_kernel(const float* __restrict__ f)
{
    __shared__ float tile[32][33];
    int n0 = blockIdx.x * 32, c0 = blockIdx.y * 32, b = blockIdx.z;
    int tx = threadIdx.x, ty = threadIdx.y;
    const float* src = f + (size_t)b * 64 * NPTS;
#pragma unroll
    for (int r = 0; r < 32; r += 8)
        tile[ty + r][tx] = src[(size_t)(c0 + ty + r) * NPTS + n0 + tx];
    __syncthreads();
    float* dst = g_featsT + (size_t)b * NPTS * 64;
#pragma unroll
    for (int r = 0; r < 32; r += 8)
        dst[(size_t)(n0 + ty + r) * 64 + c0 + tx] = tile[tx][ty + r];
}

// ---------------------------------------------------------------------------
// 2) FPS, 4-CTA cluster per batch. Each CTA owns 4096 points (1 float4/thread).
//    Exact (uncontracted) arithmetic, first-index tie-break via u64 key.
//    Per-iter all-to-all exchange of (key, winner coords) through DSMEM slots
//    (parity double-buffered), one cluster barrier per iteration.
// ---------------------------------------------------------------------------
__global__ void __launch_bounds__(1024, 1) __cluster_dims__(FPSC, 1, 1)
fps_kernel(const float* __restrict__ xyz, float* __restrict__ out)
{
    extern __shared__ float sm[];
    float* shx = sm;
    float* shy = sm + PPC;
    float* shz = sm + 2 * PPC;
    __shared__ unsigned long long slotk[2][FPSC];
    __shared__ float slotx[2][FPSC], sloty[2][FPSC], slotz[2][FPSC];
    __shared__ unsigned long long warpkey[32];

    const int tid = threadIdx.x;
    const unsigned rank = blockIdx.x & (FPSC - 1);
    const int b = blockIdx.x / FPSC;
    const float* xb = xyz + (size_t)b * NPTS * 3;
    const int base = rank * PPC;

    for (int p = tid; p < PPC; p += 1024) {
        int g = base + p;
        shx[p] = xb[3 * g]; shy[p] = xb[3 * g + 1]; shz[p] = xb[3 * g + 2];
    }
    float d0 = 1e10f, d1 = 1e10f, d2 = 1e10f, d3 = 1e10f;
    float wx = xb[0], wy = xb[1], wz = xb[2];       // first center = point 0
    float* outx = out + (size_t)b * NCTR * 3;
    __syncthreads();

    // thread0: precompute remote slot base addresses
    uint32_t a_k[FPSC], a_x[FPSC], a_y[FPSC], a_z[FPSC];
    if (tid == 0) {
        uint32_t lk = smem_u32(&slotk[0][rank]);
        uint32_t lx = smem_u32(&slotx[0][rank]);
        uint32_t ly = smem_u32(&sloty[0][rank]);
        uint32_t lz = smem_u32(&slotz[0][rank]);
#pragma unroll
        for (int r = 0; r < FPSC; r++) {
            a_k[r] = mapa32(lk, r); a_x[r] = mapa32(lx, r);
            a_y[r] = mapa32(ly, r); a_z[r] = mapa32(lz, r);
        }
    }

    for (int k = 0; k < NCTR; k++) {
        if (rank == 0 && tid == 0) {
            outx[3 * k] = wx; outx[3 * k + 1] = wy; outx[3 * k + 2] = wz;
        }
        if (k == NCTR - 1) break;

        const float cx = wx, cy = wy, cz = wz;
        float4 xv = ((const float4*)shx)[tid];
        float4 yv = ((const float4*)shy)[tid];
        float4 zv = ((const float4*)shz)[tid];
        float ax, ay, az, t0, t1, t2, t3;
        ax = __fsub_rn(xv.x, cx); ay = __fsub_rn(yv.x, cy); az = __fsub_rn(zv.x, cz);
        t0 = __fadd_rn(__fadd_rn(__fmul_rn(ax, ax), __fmul_rn(ay, ay)), __fmul_rn(az, az));
        ax = __fsub_rn(xv.y, cx); ay = __fsub_rn(yv.y, cy); az = __fsub_rn(zv.y, cz);
        t1 = __fadd_rn(__fadd_rn(__fmul_rn(ax, ax), __fmul_rn(ay, ay)), __fmul_rn(az, az));
        ax = __fsub_rn(xv.z, cx); ay = __fsub_rn(yv.z, cy); az = __fsub_rn(zv.z, cz);
        t2 = __fadd_rn(__fadd_rn(__fmul_rn(ax, ax), __fmul_rn(ay, ay)), __fmul_rn(az, az));
        ax = __fsub_rn(xv.w, cx); ay = __fsub_rn(yv.w, cy); az = __fsub_rn(zv.w, cz);
        t3 = __fadd_rn(__fadd_rn(__fmul_rn(ax, ax), __fmul_rn(ay, ay)), __fmul_rn(az, az));

        d0 = fminf(d0, t0); d1 = fminf(d1, t1);
        d2 = fminf(d2, t2); d3 = fminf(d3, t3);
        float bestv = fmaxf(fmaxf(d0, d1), fmaxf(d2, d3));
        unsigned gi = (unsigned)(base + 4 * tid);
        unsigned bi = (d0 == bestv) ? gi
                    : (d1 == bestv) ? gi + 1u
                    : (d2 == bestv) ? gi + 2u : gi + 3u;
        unsigned long long key =
            ((unsigned long long)__float_as_uint(bestv) << 32) | (unsigned)(~bi);
#pragma unroll
        for (int o = 16; o; o >>= 1) {
            unsigned long long ot = __shfl_down_sync(0xffffffffu, key, o);
            if (ot > key) key = ot;
        }
        if ((tid & 31) == 0) warpkey[tid >> 5] = key;
        __syncthreads();

        const int ph = k & 1;
        if (tid < 32) {
            unsigned long long k2 = warpkey[tid];
#pragma unroll
            for (int o = 16; o; o >>= 1) {
                unsigned long long ot = __shfl_down_sync(0xffffffffu, k2, o);
                if (ot > k2) k2 = ot;
            }
            if (tid == 0) {
                unsigned lidx = (~(unsigned)k2) - (unsigned)base;
                float bx = shx[lidx], by = shy[lidx], bz = shz[lidx];
                uint32_t off8 = (uint32_t)ph * FPSC * 8;
                uint32_t off4 = (uint32_t)ph * FPSC * 4;
#pragma unroll
                for (int r = 0; r < FPSC; r++) {
                    st_cluster_b64(a_k[r] + off8, k2);
                    st_cluster_b32(a_x[r] + off4, __float_as_uint(bx));
                    st_cluster_b32(a_y[r] + off4, __float_as_uint(by));
                    st_cluster_b32(a_z[r] + off4, __float_as_uint(bz));
                }
            }
        }
        CLUSTER_SYNC();
        unsigned long long bk = slotk[ph][0]; int ws = 0;
#pragma unroll
        for (int r = 1; r < FPSC; r++)
            if (slotk[ph][r] > bk) { bk = slotk[ph][r]; ws = r; }
        wx = slotx[ph][ws]; wy = sloty[ph][ws]; wz = slotz[ph][ws];
    }
    CLUSTER_SYNC();
}

// ---------------------------------------------------------------------------
// 3) ball query: 1 warp per center, ascending-index append with early exit.
// ---------------------------------------------------------------------------
__global__ void __launch_bounds__(256)
ballquery_kernel(const float* __restrict__ xyz, const float* __restrict__ out)
{
    int gw = (blockIdx.x * blockDim.x + threadIdx.x) >> 5;
    int lane = threadIdx.x & 31;
    if (gw >= NB * NCTR) return;
    int b = gw >> 10, j = gw & (NCTR - 1);

    const float* xb = xyz + (size_t)b * NPTS * 3;
    const float* cp = out + ((size_t)b * NCTR + j) * 3;
    float cx = cp[0], cy = cp[1], cz = cp[2];
    int* outi = g_ballidx + ((size_t)b * NCTR + j) * NSAMP;

    int cnt = 0, firstidx = 0;
    for (int c = 0; c < NPTS / 32 && cnt < NSAMP; ++c) {
        int p = c * 32 + lane;
        float x = xb[3 * p], y = xb[3 * p + 1], z = xb[3 * p + 2];
        float dx = __fsub_rn(cx, x), dy = __fsub_rn(cy, y), dz = __fsub_rn(cz, z);
        float d2 = __fadd_rn(__fadd_rn(__fmul_rn(dx, dx), __fmul_rn(dy, dy)),
                             __fmul_rn(dz, dz));
        bool in = d2 < R2;
        unsigned m = __ballot_sync(0xffffffffu, in);
        if (m) {
            if (cnt == 0) {
                int src = __ffs(m) - 1;
                firstidx = __shfl_sync(0xffffffffu, p, src);
            }
            int rank = cnt + __popc(m & ((1u << lane) - 1u));
            if (in && rank < NSAMP) outi[rank] = p;
            cnt += __popc(m);
        }
    }
    if (cnt < NSAMP && lane >= cnt) outi[lane] = firstidx;
}

// ---------------------------------------------------------------------------
// 4) gather + MLP(67->64->64->128) + maxpool, register-tiled GEMM.
//    256 threads, 8 centers/block processed as 4 chunks of 2 centers (64 samp).
//    Layout: act buffer [64][68], feats at cols 0..63, dxyz at 64..66, pad 67.
// ---------------------------------------------------------------------------
#define CPB  8
#define BUFW 68
#define OW1   0
#define OW2   (OW1 + 68 * 64)
#define OW3   (OW2 + 64 * 64)
#define OSV   (OW3 + 64 * 128)
#define OBA   (OSV + 512)
#define OBB   (OBA + 64 * BUFW)
#define OPOOL (OBB + 64 * BUFW)
#define OSIDX (OPOOL + 256)
#define MLP_SMEM_BYTES ((OSIDX + 64) * 4)

__global__ void __launch_bounds__(256, 2)
mlp_kernel(const float* __restrict__ xyz,
           const float* __restrict__ W1, const float* __restrict__ s1, const float* __restrict__ b1,
           const float* __restrict__ W2, const float* __restrict__ s2, const float* __restrict__ b2,
           const float* __restrict__ W3, const float* __restrict__ s3, const float* __restrict__ b3,
           float* __restrict__ out)
{
    extern __shared__ float smem[];
    float* W1s = smem + OW1;    // [j 0..67][o 0..63], j<64: feat j (ref i=3+j), 64..66: dxyz, 67: zero
    float* W2s = smem + OW2;    // [i][o]
    float* W3s = smem + OW3;    // [i][o 0..127]
    float* sv  = smem + OSV;    // s1 b1 s2 b2 s3 b3
    float* bufA = smem + OBA;   // [64][68]
    float* bufB = smem + OBB;   // [64][68]
    int* pooled = (int*)(smem + OPOOL);  // [2][128]
    int* sidx   = (int*)(smem + OSIDX);  // [64]

    const int t = threadIdx.x;

    for (int e = t; e < 68 * 64; e += 256) {
        int j = e >> 6, o = e & 63;
        float v = (j < 64) ? W1[o * 67 + 3 + j] : (j < 67 ? W1[o * 67 + (j - 64)] : 0.0f);
        W1s[j * 64 + o] = v;
    }
    for (int e = t; e < 64 * 64; e += 256) {
        int i = e >> 6, o = e & 63;
        W2s[i * 64 + o] = W2[o * 64 + i];
    }
    for (int e = t; e < 64 * 128; e += 256) {
        int i = e >> 7, o = e & 127;
        W3s[i * 128 + o] = W3[o * 64 + i];
    }
    if (t < 64) { sv[t] = s1[t]; sv[64 + t] = b1[t]; sv[128 + t] = s2[t]; sv[192 + t] = b2[t]; }
    if (t < 128) { sv[256 + t] = s3[t]; sv[384 + t] = b3[t]; }

    const int sg = t >> 4;      // 0..15 sample group
    const int og = t & 15;      // 0..15 output group

    for (int ch = 0; ch < CPB / 2; ++ch) {
        const int cid0 = blockIdx.x * CPB + ch * 2;

        pooled[t] = 0;
        if (t < 64) sidx[t] = g_ballidx[(size_t)(cid0 + (t >> 5)) * NSAMP + (t & 31)];
        __syncthreads();

        // ---- gather 64 samples into bufA ----
        {
            int s = t & 63, part = t >> 6;   // 4 threads per sample
            int cid = cid0 + (s >> 5);
            int bb = cid >> 10, jj = cid & (NCTR - 1);
            int pi = sidx[s];
            const float4* frow = (const float4*)(g_featsT + ((size_t)bb * NPTS + pi) * 64);
            float4* dst = (float4*)(bufA + s * BUFW);
#pragma unroll
            for (int f = 0; f < 4; ++f) dst[part * 4 + f] = frow[part * 4 + f];
            if (part == 0) {
                const float* cp = out + ((size_t)bb * NCTR + jj) * 3;
                const float* pr = xyz + ((size_t)bb * NPTS + pi) * 3;
                bufA[s * BUFW + 64] = pr[0] - cp[0];
                bufA[s * BUFW + 65] = pr[1] - cp[1];
                bufA[s * BUFW + 66] = pr[2] - cp[2];
                bufA[s * BUFW + 67] = 0.0f;
            }
        }
        __syncthreads();

        // ---- Layer 1: K=68 (padded), 64 outs ----
        {
            float acc[4][4];
#pragma unroll
            for (int si = 0; si < 4; ++si)
#pragma unroll
                for (int oj = 0; oj < 4; ++oj) acc[si][oj] = 0.0f;
            const float4* a0 = (const float4*)(bufA + (sg     ) * BUFW);
            const float4* a1 = (const float4*)(bufA + (sg + 16) * BUFW);
            const float4* a2 = (const float4*)(bufA + (sg + 32) * BUFW);
            const float4* a3 = (const float4*)(bufA + (sg + 48) * BUFW);
#pragma unroll
            for (int kk = 0; kk < 17; ++kk) {
                float4 v0 = a0[kk], v1 = a1[kk], v2 = a2[kk], v3 = a3[kk];
                float va0[4] = {v0.x, v0.y, v0.z, v0.w};
                float va1[4] = {v1.x, v1.y, v1.z, v1.w};
                float va2[4] = {v2.x, v2.y, v2.z, v2.w};
                float va3[4] = {v3.x, v3.y, v3.z, v3.w};
#pragma unroll
                for (int j = 0; j < 4; ++j) {
                    float4 w = *(const float4*)(W1s + (kk * 4 + j) * 64 + og * 4);
                    float wv[4] = {w.x, w.y, w.z, w.w};
#pragma unroll
                    for (int oj = 0; oj < 4; ++oj) {
                        acc[0][oj] = fmaf(va0[j], wv[oj], acc[0][oj]);
                        acc[1][oj] = fmaf(va1[j], wv[oj], acc[1][oj]);
                        acc[2][oj] = fmaf(va2[j], wv[oj], acc[2][oj]);
                        acc[3][oj] = fmaf(va3[j], wv[oj], acc[3][oj]);
                    }
                }
            }
#pragma unroll
            for (int si = 0; si < 4; ++si) {
                float4 r;
                int o0 = og * 4;
                r.x = fmaxf(fmaf(acc[si][0], sv[o0],     sv[64 + o0]),     0.0f);
                r.y = fmaxf(fmaf(acc[si][1], sv[o0 + 1], sv[64 + o0 + 1]), 0.0f);
                r.z = fmaxf(fmaf(acc[si][2], sv[o0 + 2], sv[64 + o0 + 2]), 0.0f);
                r.w = fmaxf(fmaf(acc[si][3], sv[o0 + 3], sv[64 + o0 + 3]), 0.0f);
                *(float4*)(bufB + (sg + 16 * si) * BUFW + o0) = r;
            }
        }
        __syncthreads();

        // ---- Layer 2: K=64, 64 outs ----
        {
            float acc[4][4];
#pragma unroll
            for (int si = 0; si < 4; ++si)
#pragma unroll
                for (int oj = 0; oj < 4; ++oj) acc[si][oj] = 0.0f;
            const float4* a0 = (const float4*)(bufB + (sg     ) * BUFW);
            const float4* a1 = (const float4*)(bufB + (sg + 16) * BUFW);
            const float4* a2 = (const float4*)(bufB + (sg + 32) * BUFW);
            const float4* a3 = (const float4*)(bufB + (sg + 48) * BUFW);
#pragma unroll
            for (int kk = 0; kk < 16; ++kk) {
                float4 v0 = a0[kk], v1 = a1[kk], v2 = a2[kk], v3 = a3[kk];
                float va0[4] = {v0.x, v0.y, v0.z, v0.w};
                float va1[4] = {v1.x, v1.y, v1.z, v1.w};
                float va2[4] = {v2.x, v2.y, v2.z, v2.w};
                float va3[4] = {v3.x, v3.y, v3.z, v3.w};
#pragma unroll
                for (int j = 0; j < 4; ++j) {
                    float4 w = *(const float4*)(W2s + (kk * 4 + j) * 64 + og * 4);
                    float wv[4] = {w.x, w.y, w.z, w.w};
#pragma unroll
                    for (int oj = 0; oj < 4; ++oj) {
                        acc[0][oj] = fmaf(va0[j], wv[oj], acc[0][oj]);
                        acc[1][oj] = fmaf(va1[j], wv[oj], acc[1][oj]);
                        acc[2][oj] = fmaf(va2[j], wv[oj], acc[2][oj]);
                        acc[3][oj] = fmaf(va3[j], wv[oj], acc[3][oj]);
                    }
                }
            }
#pragma unroll
            for (int si = 0; si < 4; ++si) {
                float4 r;
                int o0 = og * 4;
                r.x = fmaxf(fmaf(acc[si][0], sv[128 + o0],     sv[192 + o0]),     0.0f);
                r.y = fmaxf(fmaf(acc[si][1], sv[128 + o0 + 1], sv[192 + o0 + 1]), 0.0f);
                r.z = fmaxf(fmaf(acc[si][2], sv[128 + o0 + 2], sv[192 + o0 + 2]), 0.0f);
                r.w = fmaxf(fmaf(acc[si][3], sv[128 + o0 + 3], sv[192 + o0 + 3]), 0.0f);
                *(float4*)(bufA + (sg + 16 * si) * BUFW + o0) = r;
            }
        }
        __syncthreads();

        // ---- Layer 3: K=64, 128 outs, fused maxpool ----
        {
            float acc[4][8];
#pragma unroll
            for (int si = 0; si < 4; ++si)
#pragma unroll
                for (int oj = 0; oj < 8; ++oj) acc[si][oj] = 0.0f;
            const float4* a0 = (const float4*)(bufA + (sg     ) * BUFW);
            const float4* a1 = (const float4*)(bufA + (sg + 16) * BUFW);
            const float4* a2 = (const float4*)(bufA + (sg + 32) * BUFW);
            const float4* a3 = (const float4*)(bufA + (sg + 48) * BUFW);
            const int o0 = og * 8;
#pragma unroll
            for (int kk = 0; kk < 16; ++kk) {
                float4 v0 = a0[kk], v1 = a1[kk], v2 = a2[kk], v3 = a3[kk];
                float va0[4] = {v0.x, v0.y, v0.z, v0.w};
                float va1[4] = {v1.x, v1.y, v1.z, v1.w};
                float va2[4] = {v2.x, v2.y, v2.z, v2.w};
                float va3[4] = {v3.x, v3.y, v3.z, v3.w};
#pragma unroll
                for (int j = 0; j < 4; ++j) {
                    float4 wA = *(const float4*)(W3s + (kk * 4 + j) * 128 + o0);
                    float4 wB = *(const float4*)(W3s + (kk * 4 + j) * 128 + o0 + 4);
                    float wv[8] = {wA.x, wA.y, wA.z, wA.w, wB.x, wB.y, wB.z, wB.w};
#pragma unroll
                    for (int oj = 0; oj < 8; ++oj) {
                        acc[0][oj] = fmaf(va0[j], wv[oj], acc[0][oj]);
                        acc[1][oj] = fmaf(va1[j], wv[oj], acc[1][oj]);
                        acc[2][oj] = fmaf(va2[j], wv[oj], acc[2][oj]);
                        acc[3][oj] = fmaf(va3[j], wv[oj], acc[3][oj]);
                    }
                }
            }
#pragma unroll
            for (int oj = 0; oj < 8; ++oj) {
                int o = o0 + oj;
                float sc = sv[256 + o], bi = sv[384 + o];
                float y0 = fmaxf(fmaf(acc[0][oj], sc, bi), 0.0f);
                float y1 = fmaxf(fmaf(acc[1][oj], sc, bi), 0.0f);
                float y2 = fmaxf(fmaf(acc[2][oj], sc, bi), 0.0f);
                float y3 = fmaxf(fmaf(acc[3][oj], sc, bi), 0.0f);
                atomicMax(&pooled[o],       __float_as_int(fmaxf(y0, y1)));
                atomicMax(&pooled[128 + o], __float_as_int(fmaxf(y2, y3)));
            }
        }
        __syncthreads();

        // ---- write 2 centers' pooled outputs ----
        {
            int c = t >> 7, o = t & 127;
            int cid = cid0 + c;
            int bb = cid >> 10, jj = cid & (NCTR - 1);
            out[12288 + ((size_t)bb * 128 + o) * NCTR + jj] = __int_as_float(pooled[t]);
        }
        __syncthreads();
    }
}

// ---------------------------------------------------------------------------
extern "C" void kernel_launch(void* const* d_in, const int* in_sizes, int n_in,
                              void* d_out, int out_size)
{
    const float* xyz      = (const float*)d_in[0];
    const float* features = (const float*)d_in[1];
    const float* W1 = (const float*)d_in[2];
    const float* s1 = (const float*)d_in[3];
    const float* b1 = (const float*)d_in[4];
    const float* W2 = (const float*)d_in[5];
    const float* s2 = (const float*)d_in[6];
    const float* b2 = (const float*)d_in[7];
    const float* W3 = (const float*)d_in[8];
    const float* s3 = (const float*)d_in[9];
    const float* b3 = (const float*)d_in[10];
    float* out = (float*)d_out;

    cudaFuncSetAttribute(fps_kernel, cudaFuncAttributeMaxDynamicSharedMemorySize,
                         PPC * 3 * sizeof(float));
    cudaFuncSetAttribute(mlp_kernel, cudaFuncAttributeMaxDynamicSharedMemorySize,
                         MLP_SMEM_BYTES);

    transpose_kernel<<<dim3(NPTS / 32, 2, NB), dim3(32, 8)>>>(features);
    fps_kernel<<<NB * FPSC, 1024, PPC * 3 * sizeof(float)>>>(xyz, out);
    ballquery_kernel<<<(NB * NCTR * 32) / 256, 256>>>(xyz, out);
    mlp_kernel<<<(NB * NCTR) / CPB, 256, MLP_SMEM_BYTES>>>(
        xyz, W1, s1, b1, W2, s2, b2, W3, s3, b3, out);
}

// round 5
// speedup vs baseline: 1.8259x; 1.0900x over previous
#include <cuda_runtime.h>
#include <cuda_bf16.h>
#include <stdint.h>

#define NB    4
#define NPTS  16384
#define NCTR  1024
#define NSAMP 32
#define R2    0.04f

// ---------------- scratch (no allocations allowed) ----------------
__device__ float g_featsT[(size_t)NB * NPTS * 64];   // (B,N,C)
__device__ int   g_ballidx[NB * NCTR * NSAMP];

// ---------------------------------------------------------------------------
// 1) transpose features (B,64,N) -> (B,N,64)
// ---------------------------------------------------------------------------
__global__ void transpose_kernel(const float* __restrict__ f)
{
    __shared__ float tile[32][33];
    int n0 = blockIdx.x * 32, c0 = blockIdx.y * 32, b = blockIdx.z;
    int tx = threadIdx.x, ty = threadIdx.y;
    const float* src = f + (size_t)b * 64 * NPTS;
#pragma unroll
    for (int r = 0; r < 32; r += 8)
        tile[ty + r][tx] = src[(size_t)(c0 + ty + r) * NPTS + n0 + tx];
    __syncthreads();
    float* dst = g_featsT + (size_t)b * NPTS * 64;
#pragma unroll
    for (int r = 0; r < 32; r += 8)
        dst[(size_t)(n0 + ty + r) * 64 + c0 + tx] = tile[tx][ty + r];
}

// ---------------------------------------------------------------------------
// 2) FPS with exact bbox pruning. 1 CTA/batch, 1024 threads, 16 pts/thread.
//    Points counting-sorted into an 8x8x8 grid so each thread's 16 points are
//    spatially compact; thread keeps bbox + 16 dists + cached argmax key.
//    Prune rule (exact): lb2*0.99999 > cached_max  =>  no dist in the thread
//    can change this iteration => cached key/coords remain valid bitwise.
// ---------------------------------------------------------------------------
#define FPS_CTRL_OFF (3 * NPTS * 4 + NPTS * 2)          // bytes
#define FPS_SMEM     (FPS_CTRL_OFF + 2048)              // 231424 B

__global__ void __launch_bounds__(1024, 1)
fps_kernel(const float* __restrict__ xyz, float* __restrict__ out)
{
    extern __shared__ float sm[];
    float* shx = sm;
    float* shy = sm + NPTS;
    float* shz = sm + 2 * NPTS;
    uint16_t* sidx = (uint16_t*)(sm + 3 * NPTS);
    char* ctrlb = (char*)sm + FPS_CTRL_OFF;
    unsigned int* hist = (unsigned int*)ctrlb;                       // [512] setup only
    unsigned long long* warpkey = (unsigned long long*)ctrlb;        // [32] (aliases hist)
    unsigned long long* s_key = (unsigned long long*)(ctrlb + 256);
    float* s_wc = (float*)(ctrlb + 264);                             // winner coords

    const int tid = threadIdx.x;
    const int b = blockIdx.x;
    const float* xb = xyz + (size_t)b * NPTS * 3;
    float* outx = out + (size_t)b * NCTR * 3;

    // ---- counting sort into 8x8x8 cells ----
    if (tid < 512) hist[tid] = 0u;
    __syncthreads();
    for (int p = tid; p < NPTS; p += 1024) {
        float x = xb[3 * p], y = xb[3 * p + 1], z = xb[3 * p + 2];
        int cx = min(7, (int)(x * 8.0f));
        int cy = min(7, (int)(y * 8.0f));
        int cz = min(7, (int)(z * 8.0f));
        atomicAdd(&hist[(cx << 6) | (cy << 3) | cz], 1u);
    }
    __syncthreads();
    if (tid < 32) {                         // exclusive prefix over 512 bins
        unsigned v[16], s = 0;
#pragma unroll
        for (int i = 0; i < 16; i++) { v[i] = hist[tid * 16 + i]; s += v[i]; }
        unsigned run = s;
#pragma unroll
        for (int o = 1; o < 32; o <<= 1) {
            unsigned t2 = __shfl_up_sync(0xffffffffu, run, o);
            if (tid >= o) run += t2;
        }
        unsigned acc = run - s;
#pragma unroll
        for (int i = 0; i < 16; i++) { unsigned c = v[i]; hist[tid * 16 + i] = acc; acc += c; }
    }
    __syncthreads();
    for (int p = tid; p < NPTS; p += 1024) {
        float x = xb[3 * p], y = xb[3 * p + 1], z = xb[3 * p + 2];
        int cx = min(7, (int)(x * 8.0f));
        int cy = min(7, (int)(y * 8.0f));
        int cz = min(7, (int)(z * 8.0f));
        unsigned pos = atomicAdd(&hist[(cx << 6) | (cy << 3) | cz], 1u);
        shx[pos] = x; shy[pos] = y; shz[pos] = z; sidx[pos] = (uint16_t)p;
    }
    __syncthreads();

    // ---- per-thread bbox + state ----
    float lox = 1e30f, loy = 1e30f, loz = 1e30f;
    float hix = -1e30f, hiy = -1e30f, hiz = -1e30f;
    float dist[16];
#pragma unroll
    for (int j = 0; j < 16; j++) {
        float x = shx[tid * 16 + j], y = shy[tid * 16 + j], z = shz[tid * 16 + j];
        lox = fminf(lox, x); hix = fmaxf(hix, x);
        loy = fminf(loy, y); hiy = fmaxf(hiy, y);
        loz = fminf(loz, z); hiz = fmaxf(hiz, z);
        dist[j] = 10000000000.0f;
    }
    unsigned long long mykey = 0x7f80000000000000ULL;   // bestv=+inf => forced recompute
    float bx = 0.0f, by = 0.0f, bz = 0.0f;

    float wx = xb[0], wy = xb[1], wz = xb[2];           // first center = point 0

    const float4* px4 = (const float4*)shx + tid * 4;
    const float4* py4 = (const float4*)shy + tid * 4;
    const float4* pz4 = (const float4*)shz + tid * 4;

    for (int k = 0; k < NCTR; k++) {
        if (tid == 0) {
            outx[3 * k] = wx; outx[3 * k + 1] = wy; outx[3 * k + 2] = wz;
        }
        if (k == NCTR - 1) break;

        // ---- exact prune test ----
        float lbx = fmaxf(0.0f, fmaxf(lox - wx, wx - hix));
        float lby = fmaxf(0.0f, fmaxf(loy - wy, wy - hiy));
        float lbz = fmaxf(0.0f, fmaxf(loz - wz, wz - hiz));
        float lb2 = lbx * lbx + lby * lby + lbz * lbz;
        float bestv = __uint_as_float((unsigned)(mykey >> 32));
        bool re = !(lb2 * 0.99999f > bestv);

        if (re) {
            unsigned long long nk = 0;
            float nbx = 0.0f, nby = 0.0f, nbz = 0.0f;
#pragma unroll
            for (int q = 0; q < 4; q++) {
                float4 xv = px4[q], yv = py4[q], zv = pz4[q];
                float xs[4] = {xv.x, xv.y, xv.z, xv.w};
                float ys[4] = {yv.x, yv.y, yv.z, yv.w};
                float zs[4] = {zv.x, zv.y, zv.z, zv.w};
#pragma unroll
                for (int c = 0; c < 4; c++) {
                    int j = q * 4 + c;
                    float dx = __fsub_rn(xs[c], wx);
                    float dy = __fsub_rn(ys[c], wy);
                    float dz = __fsub_rn(zs[c], wz);
                    float d = __fadd_rn(__fadd_rn(__fmul_rn(dx, dx), __fmul_rn(dy, dy)),
                                        __fmul_rn(dz, dz));
                    float nd = fminf(dist[j], d);
                    dist[j] = nd;
                    unsigned oi = (unsigned)sidx[tid * 16 + j];
                    unsigned long long pk =
                        ((unsigned long long)__float_as_uint(nd) << 32) | (unsigned)(~oi);
                    if (pk > nk) { nk = pk; nbx = xs[c]; nby = ys[c]; nbz = zs[c]; }
                }
            }
            mykey = nk; bx = nbx; by = nby; bz = nbz;
        }

        // ---- reduce: warp (skipped if whole warp pruned), then cross-warp ----
        unsigned m = __ballot_sync(0xffffffffu, re);
        if (m) {
            unsigned long long r = mykey;
#pragma unroll
            for (int o = 16; o; o >>= 1) {
                unsigned long long t2 = __shfl_down_sync(0xffffffffu, r, o);
                if (t2 > r) r = t2;
            }
            if ((tid & 31) == 0) warpkey[tid >> 5] = r;
        }
        __syncthreads();
        if (tid < 32) {
            unsigned long long k2 = warpkey[tid];
#pragma unroll
            for (int o = 16; o; o >>= 1) {
                unsigned long long t2 = __shfl_down_sync(0xffffffffu, k2, o);
                if (t2 > k2) k2 = t2;
            }
            if (tid == 0) *s_key = k2;
        }
        __syncthreads();
        unsigned long long gk = *s_key;
        if (mykey == gk) { s_wc[0] = bx; s_wc[1] = by; s_wc[2] = bz; }
        __syncthreads();
        wx = s_wc[0]; wy = s_wc[1]; wz = s_wc[2];
    }
}

// ---------------------------------------------------------------------------
// 3) ball query: 1 warp per center, ascending-index append with early exit.
// ---------------------------------------------------------------------------
__global__ void __launch_bounds__(256)
ballquery_kernel(const float* __restrict__ xyz, const float* __restrict__ out)
{
    int gw = (blockIdx.x * blockDim.x + threadIdx.x) >> 5;
    int lane = threadIdx.x & 31;
    if (gw >= NB * NCTR) return;
    int b = gw >> 10, j = gw & (NCTR - 1);

    const float* xb = xyz + (size_t)b * NPTS * 3;
    const float* cp = out + ((size_t)b * NCTR + j) * 3;
    float cx = cp[0], cy = cp[1], cz = cp[2];
    int* outi = g_ballidx + ((size_t)b * NCTR + j) * NSAMP;

    int cnt = 0, firstidx = 0;
    for (int c = 0; c < NPTS / 32 && cnt < NSAMP; ++c) {
        int p = c * 32 + lane;
        float x = xb[3 * p], y = xb[3 * p + 1], z = xb[3 * p + 2];
        float dx = __fsub_rn(cx, x), dy = __fsub_rn(cy, y), dz = __fsub_rn(cz, z);
        float d2 = __fadd_rn(__fadd_rn(__fmul_rn(dx, dx), __fmul_rn(dy, dy)),
                             __fmul_rn(dz, dz));
        bool in = d2 < R2;
        unsigned m = __ballot_sync(0xffffffffu, in);
        if (m) {
            if (cnt == 0) {
                int src = __ffs(m) - 1;
                firstidx = __shfl_sync(0xffffffffu, p, src);
            }
            int rank = cnt + __popc(m & ((1u << lane) - 1u));
            if (in && rank < NSAMP) outi[rank] = p;
            cnt += __popc(m);
        }
    }
    if (cnt < NSAMP && lane >= cnt) outi[lane] = firstidx;
}

// ---------------------------------------------------------------------------
// 4) gather + MLP(67->64->64->128) + maxpool, register-tiled GEMM.
// ---------------------------------------------------------------------------
#define CPB  8
#define BUFW 68
#define OW1   0
#define OW2   (OW1 + 68 * 64)
#define OW3   (OW2 + 64 * 64)
#define OSV   (OW3 + 64 * 128)
#define OBA   (OSV + 512)
#define OBB   (OBA + 64 * BUFW)
#define OPOOL (OBB + 64 * BUFW)
#define OSIDX (OPOOL + 256)
#define MLP_SMEM_BYTES ((OSIDX + 64) * 4)

__global__ void __launch_bounds__(256, 2)
mlp_kernel(const float* __restrict__ xyz,
           const float* __restrict__ W1, const float* __restrict__ s1, const float* __restrict__ b1,
           const float* __restrict__ W2, const float* __restrict__ s2, const float* __restrict__ b2,
           const float* __restrict__ W3, const float* __restrict__ s3, const float* __restrict__ b3,
           float* __restrict__ out)
{
    extern __shared__ float smem[];
    float* W1s = smem + OW1;
    float* W2s = smem + OW2;
    float* W3s = smem + OW3;
    float* sv  = smem + OSV;
    float* bufA = smem + OBA;
    float* bufB = smem + OBB;
    int* pooled = (int*)(smem + OPOOL);
    int* sidx   = (int*)(smem + OSIDX);

    const int t = threadIdx.x;

    for (int e = t; e < 68 * 64; e += 256) {
        int j = e >> 6, o = e & 63;
        float v = (j < 64) ? W1[o * 67 + 3 + j] : (j < 67 ? W1[o * 67 + (j - 64)] : 0.0f);
        W1s[j * 64 + o] = v;
    }
    for (int e = t; e < 64 * 64; e += 256) {
        int i = e >> 6, o = e & 63;
        W2s[i * 64 + o] = W2[o * 64 + i];
    }
    for (int e = t; e < 64 * 128; e += 256) {
        int i = e >> 7, o = e & 127;
        W3s[i * 128 + o] = W3[o * 64 + i];
    }
    if (t < 64) { sv[t] = s1[t]; sv[64 + t] = b1[t]; sv[128 + t] = s2[t]; sv[192 + t] = b2[t]; }
    if (t < 128) { sv[256 + t] = s3[t]; sv[384 + t] = b3[t]; }

    const int sg = t >> 4;
    const int og = t & 15;

    for (int ch = 0; ch < CPB / 2; ++ch) {
        const int cid0 = blockIdx.x * CPB + ch * 2;

        pooled[t] = 0;
        if (t < 64) sidx[t] = g_ballidx[(size_t)(cid0 + (t >> 5)) * NSAMP + (t & 31)];
        __syncthreads();

        {
            int s = t & 63, part = t >> 6;
            int cid = cid0 + (s >> 5);
            int bb = cid >> 10, jj = cid & (NCTR - 1);
            int pi = sidx[s];
            const float4* frow = (const float4*)(g_featsT + ((size_t)bb * NPTS + pi) * 64);
            float4* dst = (float4*)(bufA + s * BUFW);
#pragma unroll
            for (int f = 0; f < 4; ++f) dst[part * 4 + f] = frow[part * 4 + f];
            if (part == 0) {
                const float* cp = out + ((size_t)bb * NCTR + jj) * 3;
                const float* pr = xyz + ((size_t)bb * NPTS + pi) * 3;
                bufA[s * BUFW + 64] = pr[0] - cp[0];
                bufA[s * BUFW + 65] = pr[1] - cp[1];
                bufA[s * BUFW + 66] = pr[2] - cp[2];
                bufA[s * BUFW + 67] = 0.0f;
            }
        }
        __syncthreads();

        {   // Layer 1: K=68 padded
            float acc[4][4];
#pragma unroll
            for (int si = 0; si < 4; ++si)
#pragma unroll
                for (int oj = 0; oj < 4; ++oj) acc[si][oj] = 0.0f;
            const float4* a0 = (const float4*)(bufA + (sg     ) * BUFW);
            const float4* a1 = (const float4*)(bufA + (sg + 16) * BUFW);
            const float4* a2 = (const float4*)(bufA + (sg + 32) * BUFW);
            const float4* a3 = (const float4*)(bufA + (sg + 48) * BUFW);
#pragma unroll
            for (int kk = 0; kk < 17; ++kk) {
                float4 v0 = a0[kk], v1 = a1[kk], v2 = a2[kk], v3 = a3[kk];
                float va0[4] = {v0.x, v0.y, v0.z, v0.w};
                float va1[4] = {v1.x, v1.y, v1.z, v1.w};
                float va2[4] = {v2.x, v2.y, v2.z, v2.w};
                float va3[4] = {v3.x, v3.y, v3.z, v3.w};
#pragma unroll
                for (int j = 0; j < 4; ++j) {
                    float4 w = *(const float4*)(W1s + (kk * 4 + j) * 64 + og * 4);
                    float wv[4] = {w.x, w.y, w.z, w.w};
#pragma unroll
                    for (int oj = 0; oj < 4; ++oj) {
                        acc[0][oj] = fmaf(va0[j], wv[oj], acc[0][oj]);
                        acc[1][oj] = fmaf(va1[j], wv[oj], acc[1][oj]);
                        acc[2][oj] = fmaf(va2[j], wv[oj], acc[2][oj]);
                        acc[3][oj] = fmaf(va3[j], wv[oj], acc[3][oj]);
                    }
                }
            }
#pragma unroll
            for (int si = 0; si < 4; ++si) {
                float4 r;
                int o0 = og * 4;
                r.x = fmaxf(fmaf(acc[si][0], sv[o0],     sv[64 + o0]),     0.0f);
                r.y = fmaxf(fmaf(acc[si][1], sv[o0 + 1], sv[64 + o0 + 1]), 0.0f);
                r.z = fmaxf(fmaf(acc[si][2], sv[o0 + 2], sv[64 + o0 + 2]), 0.0f);
                r.w = fmaxf(fmaf(acc[si][3], sv[o0 + 3], sv[64 + o0 + 3]), 0.0f);
                *(float4*)(bufB + (sg + 16 * si) * BUFW + o0) = r;
            }
        }
        __syncthreads();

        {   // Layer 2
            float acc[4][4];
#pragma unroll
            for (int si = 0; si < 4; ++si)
#pragma unroll
                for (int oj = 0; oj < 4; ++oj) acc[si][oj] = 0.0f;
            const float4* a0 = (const float4*)(bufB + (sg     ) * BUFW);
            const float4* a1 = (const float4*)(bufB + (sg + 16) * BUFW);
            const float4* a2 = (const float4*)(bufB + (sg + 32) * BUFW);
            const float4* a3 = (const float4*)(bufB + (sg + 48) * BUFW);
#pragma unroll
            for (int kk = 0; kk < 16; ++kk) {
                float4 v0 = a0[kk], v1 = a1[kk], v2 = a2[kk], v3 = a3[kk];
                float va0[4] = {v0.x, v0.y, v0.z, v0.w};
                float va1[4] = {v1.x, v1.y, v1.z, v1.w};
                float va2[4] = {v2.x, v2.y, v2.z, v2.w};
                float va3[4] = {v3.x, v3.y, v3.z, v3.w};
#pragma unroll
                for (int j = 0; j < 4; ++j) {
                    float4 w = *(const float4*)(W2s + (kk * 4 + j) * 64 + og * 4);
                    float wv[4] = {w.x, w.y, w.z, w.w};
#pragma unroll
                    for (int oj = 0; oj < 4; ++oj) {
                        acc[0][oj] = fmaf(va0[j], wv[oj], acc[0][oj]);
                        acc[1][oj] = fmaf(va1[j], wv[oj], acc[1][oj]);
                        acc[2][oj] = fmaf(va2[j], wv[oj], acc[2][oj]);
                        acc[3][oj] = fmaf(va3[j], wv[oj], acc[3][oj]);
                    }
                }
            }
#pragma unroll
            for (int si = 0; si < 4; ++si) {
                float4 r;
                int o0 = og * 4;
                r.x = fmaxf(fmaf(acc[si][0], sv[128 + o0],     sv[192 + o0]),     0.0f);
                r.y = fmaxf(fmaf(acc[si][1], sv[128 + o0 + 1], sv[192 + o0 + 1]), 0.0f);
                r.z = fmaxf(fmaf(acc[si][2], sv[128 + o0 + 2], sv[192 + o0 + 2]), 0.0f);
                r.w = fmaxf(fmaf(acc[si][3], sv[128 + o0 + 3], sv[192 + o0 + 3]), 0.0f);
                *(float4*)(bufA + (sg + 16 * si) * BUFW + o0) = r;
            }
        }
        __syncthreads();

        {   // Layer 3 + fused maxpool
            float acc[4][8];
#pragma unroll
            for (int si = 0; si < 4; ++si)
#pragma unroll
                for (int oj = 0; oj < 8; ++oj) acc[si][oj] = 0.0f;
            const float4* a0 = (const float4*)(bufA + (sg     ) * BUFW);
            const float4* a1 = (const float4*)(bufA + (sg + 16) * BUFW);
            const float4* a2 = (const float4*)(bufA + (sg + 32) * BUFW);
            const float4* a3 = (const float4*)(bufA + (sg + 48) * BUFW);
            const int o0 = og * 8;
#pragma unroll
            for (int kk = 0; kk < 16; ++kk) {
                float4 v0 = a0[kk], v1 = a1[kk], v2 = a2[kk], v3 = a3[kk];
                float va0[4] = {v0.x, v0.y, v0.z, v0.w};
                float va1[4] = {v1.x, v1.y, v1.z, v1.w};
                float va2[4] = {v2.x, v2.y, v2.z, v2.w};
                float va3[4] = {v3.x, v3.y, v3.z, v3.w};
#pragma unroll
                for (int j = 0; j < 4; ++j) {
                    float4 wA = *(const float4*)(W3s + (kk * 4 + j) * 128 + o0);
                    float4 wB = *(const float4*)(W3s + (kk * 4 + j) * 128 + o0 + 4);
                    float wv[8] = {wA.x, wA.y, wA.z, wA.w, wB.x, wB.y, wB.z, wB.w};
#pragma unroll
                    for (int oj = 0; oj < 8; ++oj) {
                        acc[0][oj] = fmaf(va0[j], wv[oj], acc[0][oj]);
                        acc[1][oj] = fmaf(va1[j], wv[oj], acc[1][oj]);
                        acc[2][oj] = fmaf(va2[j], wv[oj], acc[2][oj]);
                        acc[3][oj] = fmaf(va3[j], wv[oj], acc[3][oj]);
                    }
                }
            }
#pragma unroll
            for (int oj = 0; oj < 8; ++oj) {
                int o = o0 + oj;
                float sc = sv[256 + o], bi = sv[384 + o];
                float y0 = fmaxf(fmaf(acc[0][oj], sc, bi), 0.0f);
                float y1 = fmaxf(fmaf(acc[1][oj], sc, bi), 0.0f);
                float y2 = fmaxf(fmaf(acc[2][oj], sc, bi), 0.0f);
                float y3 = fmaxf(fmaf(acc[3][oj], sc, bi), 0.0f);
                atomicMax(&pooled[o],       __float_as_int(fmaxf(y0, y1)));
                atomicMax(&pooled[128 + o], __float_as_int(fmaxf(y2, y3)));
            }
        }
        __syncthreads();

        {
            int c = t >> 7, o = t & 127;
            int cid = cid0 + c;
            int bb = cid >> 10, jj = cid & (NCTR - 1);
            out[12288 + ((size_t)bb * 128 + o) * NCTR + jj] = __int_as_float(pooled[t]);
        }
        __syncthreads();
    }
}

// ---------------------------------------------------------------------------
extern "C" void kernel_launch(void* const* d_in, const int* in_sizes, int n_in,
                              void* d_out, int out_size)
{
    const float* xyz      = (const float*)d_in[0];
    const float* features = (const float*)d_in[1];
    const float* W1 = (const float*)d_in[2];
    const float* s1 = (const float*)d_in[3];
    const float* b1 = (const float*)d_in[4];
    const float* W2 = (const float*)d_in[5];
    const float* s2 = (const float*)d_in[6];
    const float* b2 = (const float*)d_in[7];
    const float* W3 = (const float*)d_in[8];
    const float* s3 = (const float*)d_in[9];
    const float* b3 = (const float*)d_in[10];
    float* out = (float*)d_out;

    cudaFuncSetAttribute(fps_kernel, cudaFuncAttributeMaxDynamicSharedMemorySize,
                         FPS_SMEM);
    cudaFuncSetAttribute(mlp_kernel, cudaFuncAttributeMaxDynamicSharedMemorySize,
                         MLP_SMEM_BYTES);

    transpose_kernel<<<dim3(NPTS / 32, 2, NB), dim3(32, 8)>>>(features);
    fps_kernel<<<NB, 1024, FPS_SMEM>>>(xyz, out);
    ballquery_kernel<<<(NB * NCTR * 32) / 256, 256>>>(xyz, out);
    mlp_kernel<<<(NB * NCTR) / CPB, 256, MLP_SMEM_BYTES>>>(
        xyz, W1, s1, b1, W2, s2, b2, W3, s3, b3, out);
}

// round 6
// speedup vs baseline: 2.0446x; 1.1198x over previous
#include <cuda_runtime.h>
#include <cuda_bf16.h>
#include <stdint.h>

#define NB    4
#define NPTS  16384
#define NCTR  1024
#define NSAMP 32
#define R2    0.04f

// ---------------- scratch (no allocations allowed) ----------------
__device__ float g_featsT[(size_t)NB * NPTS * 64];   // (B,N,C)
__device__ int   g_ballidx[NB * NCTR * NSAMP];

// ---------------------------------------------------------------------------
// 1) transpose features (B,64,N) -> (B,N,64)
// ---------------------------------------------------------------------------
__global__ void transpose_kernel(const float* __restrict__ f)
{
    __shared__ float tile[32][33];
    int n0 = blockIdx.x * 32, c0 = blockIdx.y * 32, b = blockIdx.z;
    int tx = threadIdx.x, ty = threadIdx.y;
    const float* src = f + (size_t)b * 64 * NPTS;
#pragma unroll
    for (int r = 0; r < 32; r += 8)
        tile[ty + r][tx] = src[(size_t)(c0 + ty + r) * NPTS + n0 + tx];
    __syncthreads();
    float* dst = g_featsT + (size_t)b * NPTS * 64;
#pragma unroll
    for (int r = 0; r < 32; r += 8)
        dst[(size_t)(n0 + ty + r) * 64 + c0 + tx] = tile[tx][ty + r];
}

// ---------------------------------------------------------------------------
// 2) FPS with exact bbox pruning + redux.sync 2-barrier reduction.
//    1 CTA/batch, 1024 threads, 16 pts/thread, counting-sorted into 8x8x8
//    cells. Key = (dist_bits << 32) | (16383 - orig_idx): max-key == argmax
//    with first-original-index tie-break, and keys are globally unique.
// ---------------------------------------------------------------------------
#define FPS_CTRL_OFF (3 * NPTS * 4 + NPTS * 2)          // bytes
#define FPS_SMEM     (FPS_CTRL_OFF + 2048)              // 231424 B

__global__ void __launch_bounds__(1024, 1)
fps_kernel(const float* __restrict__ xyz, float* __restrict__ out)
{
    extern __shared__ float sm[];
    float* shx = sm;
    float* shy = sm + NPTS;
    float* shz = sm + 2 * NPTS;
    uint16_t* sidx = (uint16_t*)(sm + 3 * NPTS);
    unsigned int* ctrl = (unsigned int*)((char*)sm + FPS_CTRL_OFF);  // 512 u32
    unsigned int* hist = ctrl;             // setup only
    // post-sort aliases (all rewritten before first read):
    unsigned int* wkHi = ctrl;             // [32]
    unsigned int* wkLo = ctrl + 32;        // [32]
    float* warpx = (float*)(ctrl + 64);    // [32]
    float* warpy = (float*)(ctrl + 96);
    float* warpz = (float*)(ctrl + 128);
    float* s_wc  = (float*)(ctrl + 160);   // [3]

    const int tid = threadIdx.x;
    const int b = blockIdx.x;
    const float* xb = xyz + (size_t)b * NPTS * 3;
    float* outx = out + (size_t)b * NCTR * 3;

    // ---- counting sort into 8x8x8 cells ----
    if (tid < 512) hist[tid] = 0u;
    __syncthreads();
    for (int p = tid; p < NPTS; p += 1024) {
        float x = xb[3 * p], y = xb[3 * p + 1], z = xb[3 * p + 2];
        int cx = min(7, (int)(x * 8.0f));
        int cy = min(7, (int)(y * 8.0f));
        int cz = min(7, (int)(z * 8.0f));
        atomicAdd(&hist[(cx << 6) | (cy << 3) | cz], 1u);
    }
    __syncthreads();
    if (tid < 32) {                         // exclusive prefix over 512 bins
        unsigned v[16], s = 0;
#pragma unroll
        for (int i = 0; i < 16; i++) { v[i] = hist[tid * 16 + i]; s += v[i]; }
        unsigned run = s;
#pragma unroll
        for (int o = 1; o < 32; o <<= 1) {
            unsigned t2 = __shfl_up_sync(0xffffffffu, run, o);
            if (tid >= o) run += t2;
        }
        unsigned acc = run - s;
#pragma unroll
        for (int i = 0; i < 16; i++) { unsigned c = v[i]; hist[tid * 16 + i] = acc; acc += c; }
    }
    __syncthreads();
    for (int p = tid; p < NPTS; p += 1024) {
        float x = xb[3 * p], y = xb[3 * p + 1], z = xb[3 * p + 2];
        int cx = min(7, (int)(x * 8.0f));
        int cy = min(7, (int)(y * 8.0f));
        int cz = min(7, (int)(z * 8.0f));
        unsigned pos = atomicAdd(&hist[(cx << 6) | (cy << 3) | cz], 1u);
        shx[pos] = x; shy[pos] = y; shz[pos] = z; sidx[pos] = (uint16_t)p;
    }
    __syncthreads();

    // ---- per-thread state: bbox, dists, packed inverse indices ----
    float lox = 1e30f, loy = 1e30f, loz = 1e30f;
    float hix = -1e30f, hiy = -1e30f, hiz = -1e30f;
    float dist[16];
    unsigned invp[8];                      // (16383 - orig_idx) as packed u16 pairs
#pragma unroll
    for (int j = 0; j < 16; j++) {
        float x = shx[tid * 16 + j], y = shy[tid * 16 + j], z = shz[tid * 16 + j];
        lox = fminf(lox, x); hix = fmaxf(hix, x);
        loy = fminf(loy, y); hiy = fmaxf(hiy, y);
        loz = fminf(loz, z); hiz = fmaxf(hiz, z);
        dist[j] = 10000000000.0f;
        unsigned iv = 16383u - (unsigned)sidx[tid * 16 + j];
        if ((j & 1) == 0) invp[j >> 1] = iv;
        else              invp[j >> 1] |= iv << 16;
    }
    unsigned myHi = 0x7f800000u, myLo = 0u;   // +inf => forced recompute on iter 0
    float bx = 0.0f, by = 0.0f, bz = 0.0f;

    float wx = xb[0], wy = xb[1], wz = xb[2]; // first center = point 0

    const float4* px4 = (const float4*)shx + tid * 4;
    const float4* py4 = (const float4*)shy + tid * 4;
    const float4* pz4 = (const float4*)shz + tid * 4;
    const int lane = tid & 31, w = tid >> 5;

    for (int k = 0; k < NCTR; k++) {
        if (tid == 0) {
            outx[3 * k] = wx; outx[3 * k + 1] = wy; outx[3 * k + 2] = wz;
        }
        if (k == NCTR - 1) break;

        // ---- exact prune test ----
        float lbx = fmaxf(0.0f, fmaxf(lox - wx, wx - hix));
        float lby = fmaxf(0.0f, fmaxf(loy - wy, wy - hiy));
        float lbz = fmaxf(0.0f, fmaxf(loz - wz, wz - hiz));
        float lb2 = lbx * lbx + lby * lby + lbz * lbz;
        bool re = !(lb2 * 0.99999f > __uint_as_float(myHi));

        if (re) {
            unsigned long long nk = 0;
            int nj = 0;
#pragma unroll
            for (int q = 0; q < 4; q++) {
                float4 xv = px4[q], yv = py4[q], zv = pz4[q];
                float xs[4] = {xv.x, xv.y, xv.z, xv.w};
                float ys[4] = {yv.x, yv.y, yv.z, yv.w};
                float zs[4] = {zv.x, zv.y, zv.z, zv.w};
#pragma unroll
                for (int c = 0; c < 4; c++) {
                    const int j = q * 4 + c;
                    float dx = __fsub_rn(xs[c], wx);
                    float dy = __fsub_rn(ys[c], wy);
                    float dz = __fsub_rn(zs[c], wz);
                    float d = __fadd_rn(__fadd_rn(__fmul_rn(dx, dx), __fmul_rn(dy, dy)),
                                        __fmul_rn(dz, dz));
                    float nd = fminf(dist[j], d);
                    dist[j] = nd;
                    unsigned iv = (j & 1) ? (invp[j >> 1] >> 16)
                                          : (invp[j >> 1] & 0xffffu);
                    unsigned long long pk =
                        ((unsigned long long)__float_as_uint(nd) << 32) | iv;
                    if (pk > nk) { nk = pk; nj = j; }
                }
            }
            myHi = (unsigned)(nk >> 32); myLo = (unsigned)nk;
            bx = shx[tid * 16 + nj]; by = shy[tid * 16 + nj]; bz = shz[tid * 16 + nj];
        }

        // ---- warp reduce via redux (skipped if whole warp pruned) ----
        unsigned m = __ballot_sync(0xffffffffu, re);
        if (m) {
            unsigned wm = __reduce_max_sync(0xffffffffu, myHi);
            unsigned cand = (myHi == wm) ? myLo : 0u;
            unsigned im = __reduce_max_sync(0xffffffffu, cand);
            if (myHi == wm && myLo == im) {      // unique winning lane
                wkHi[w] = wm; wkLo[w] = im;
                warpx[w] = bx; warpy[w] = by; warpz[w] = bz;
            }
        }
        __syncthreads();

        // ---- cross-warp reduce (warp 0) ----
        if (tid < 32) {
            unsigned vh = wkHi[tid], vl = wkLo[tid];
            unsigned wm = __reduce_max_sync(0xffffffffu, vh);
            unsigned cand = (vh == wm) ? vl : 0u;
            unsigned im = __reduce_max_sync(0xffffffffu, cand);
            if (vh == wm && vl == im) {          // unique winning warp-slot
                s_wc[0] = warpx[tid]; s_wc[1] = warpy[tid]; s_wc[2] = warpz[tid];
            }
        }
        __syncthreads();
        wx = s_wc[0]; wy = s_wc[1]; wz = s_wc[2];
    }
}

// ---------------------------------------------------------------------------
// 3) ball query: 1 warp per center, ascending-index append with early exit.
// ---------------------------------------------------------------------------
__global__ void __launch_bounds__(256)
ballquery_kernel(const float* __restrict__ xyz, const float* __restrict__ out)
{
    int gw = (blockIdx.x * blockDim.x + threadIdx.x) >> 5;
    int lane = threadIdx.x & 31;
    if (gw >= NB * NCTR) return;
    int b = gw >> 10, j = gw & (NCTR - 1);

    const float* xb = xyz + (size_t)b * NPTS * 3;
    const float* cp = out + ((size_t)b * NCTR + j) * 3;
    float cx = cp[0], cy = cp[1], cz = cp[2];
    int* outi = g_ballidx + ((size_t)b * NCTR + j) * NSAMP;

    int cnt = 0, firstidx = 0;
    for (int c = 0; c < NPTS / 32 && cnt < NSAMP; ++c) {
        int p = c * 32 + lane;
        float x = xb[3 * p], y = xb[3 * p + 1], z = xb[3 * p + 2];
        float dx = __fsub_rn(cx, x), dy = __fsub_rn(cy, y), dz = __fsub_rn(cz, z);
        float d2 = __fadd_rn(__fadd_rn(__fmul_rn(dx, dx), __fmul_rn(dy, dy)),
                             __fmul_rn(dz, dz));
        bool in = d2 < R2;
        unsigned m = __ballot_sync(0xffffffffu, in);
        if (m) {
            if (cnt == 0) {
                int src = __ffs(m) - 1;
                firstidx = __shfl_sync(0xffffffffu, p, src);
            }
            int rank = cnt + __popc(m & ((1u << lane) - 1u));
            if (in && rank < NSAMP) outi[rank] = p;
            cnt += __popc(m);
        }
    }
    if (cnt < NSAMP && lane >= cnt) outi[lane] = firstidx;
}

// ---------------------------------------------------------------------------
// 4) gather + MLP(67->64->64->128) + maxpool, register-tiled GEMM.
// ---------------------------------------------------------------------------
#define CPB  8
#define BUFW 68
#define OW1   0
#define OW2   (OW1 + 68 * 64)
#define OW3   (OW2 + 64 * 64)
#define OSV   (OW3 + 64 * 128)
#define OBA   (OSV + 512)
#define OBB   (OBA + 64 * BUFW)
#define OPOOL (OBB + 64 * BUFW)
#define OSIDX (OPOOL + 256)
#define MLP_SMEM_BYTES ((OSIDX + 64) * 4)

__global__ void __launch_bounds__(256, 2)
mlp_kernel(const float* __restrict__ xyz,
           const float* __restrict__ W1, const float* __restrict__ s1, const float* __restrict__ b1,
           const float* __restrict__ W2, const float* __restrict__ s2, const float* __restrict__ b2,
           const float* __restrict__ W3, const float* __restrict__ s3, const float* __restrict__ b3,
           float* __restrict__ out)
{
    extern __shared__ float smem[];
    float* W1s = smem + OW1;
    float* W2s = smem + OW2;
    float* W3s = smem + OW3;
    float* sv  = smem + OSV;
    float* bufA = smem + OBA;
    float* bufB = smem + OBB;
    int* pooled = (int*)(smem + OPOOL);
    int* sidx   = (int*)(smem + OSIDX);

    const int t = threadIdx.x;

    for (int e = t; e < 68 * 64; e += 256) {
        int j = e >> 6, o = e & 63;
        float v = (j < 64) ? W1[o * 67 + 3 + j] : (j < 67 ? W1[o * 67 + (j - 64)] : 0.0f);
        W1s[j * 64 + o] = v;
    }
    for (int e = t; e < 64 * 64; e += 256) {
        int i = e >> 6, o = e & 63;
        W2s[i * 64 + o] = W2[o * 64 + i];
    }
    for (int e = t; e < 64 * 128; e += 256) {
        int i = e >> 7, o = e & 127;
        W3s[i * 128 + o] = W3[o * 64 + i];
    }
    if (t < 64) { sv[t] = s1[t]; sv[64 + t] = b1[t]; sv[128 + t] = s2[t]; sv[192 + t] = b2[t]; }
    if (t < 128) { sv[256 + t] = s3[t]; sv[384 + t] = b3[t]; }

    const int sg = t >> 4;
    const int og = t & 15;

    for (int ch = 0; ch < CPB / 2; ++ch) {
        const int cid0 = blockIdx.x * CPB + ch * 2;

        pooled[t] = 0;
        if (t < 64) sidx[t] = g_ballidx[(size_t)(cid0 + (t >> 5)) * NSAMP + (t & 31)];
        __syncthreads();

        {
            int s = t & 63, part = t >> 6;
            int cid = cid0 + (s >> 5);
            int bb = cid >> 10, jj = cid & (NCTR - 1);
            int pi = sidx[s];
            const float4* frow = (const float4*)(g_featsT + ((size_t)bb * NPTS + pi) * 64);
            float4* dst = (float4*)(bufA + s * BUFW);
#pragma unroll
            for (int f = 0; f < 4; ++f) dst[part * 4 + f] = frow[part * 4 + f];
            if (part == 0) {
                const float* cp = out + ((size_t)bb * NCTR + jj) * 3;
                const float* pr = xyz + ((size_t)bb * NPTS + pi) * 3;
                bufA[s * BUFW + 64] = pr[0] - cp[0];
                bufA[s * BUFW + 65] = pr[1] - cp[1];
                bufA[s * BUFW + 66] = pr[2] - cp[2];
                bufA[s * BUFW + 67] = 0.0f;
            }
        }
        __syncthreads();

        {   // Layer 1: K=68 padded
            float acc[4][4];
#pragma unroll
            for (int si = 0; si < 4; ++si)
#pragma unroll
                for (int oj = 0; oj < 4; ++oj) acc[si][oj] = 0.0f;
            const float4* a0 = (const float4*)(bufA + (sg     ) * BUFW);
            const float4* a1 = (const float4*)(bufA + (sg + 16) * BUFW);
            const float4* a2 = (const float4*)(bufA + (sg + 32) * BUFW);
            const float4* a3 = (const float4*)(bufA + (sg + 48) * BUFW);
#pragma unroll
            for (int kk = 0; kk < 17; ++kk) {
                float4 v0 = a0[kk], v1 = a1[kk], v2 = a2[kk], v3 = a3[kk];
                float va0[4] = {v0.x, v0.y, v0.z, v0.w};
                float va1[4] = {v1.x, v1.y, v1.z, v1.w};
                float va2[4] = {v2.x, v2.y, v2.z, v2.w};
                float va3[4] = {v3.x, v3.y, v3.z, v3.w};
#pragma unroll
                for (int j = 0; j < 4; ++j) {
                    float4 w = *(const float4*)(W1s + (kk * 4 + j) * 64 + og * 4);
                    float wv[4] = {w.x, w.y, w.z, w.w};
#pragma unroll
                    for (int oj = 0; oj < 4; ++oj) {
                        acc[0][oj] = fmaf(va0[j], wv[oj], acc[0][oj]);
                        acc[1][oj] = fmaf(va1[j], wv[oj], acc[1][oj]);
                        acc[2][oj] = fmaf(va2[j], wv[oj], acc[2][oj]);
                        acc[3][oj] = fmaf(va3[j], wv[oj], acc[3][oj]);
                    }
                }
            }
#pragma unroll
            for (int si = 0; si < 4; ++si) {
                float4 r;
                int o0 = og * 4;
                r.x = fmaxf(fmaf(acc[si][0], sv[o0],     sv[64 + o0]),     0.0f);
                r.y = fmaxf(fmaf(acc[si][1], sv[o0 + 1], sv[64 + o0 + 1]), 0.0f);
                r.z = fmaxf(fmaf(acc[si][2], sv[o0 + 2], sv[64 + o0 + 2]), 0.0f);
                r.w = fmaxf(fmaf(acc[si][3], sv[o0 + 3], sv[64 + o0 + 3]), 0.0f);
                *(float4*)(bufB + (sg + 16 * si) * BUFW + o0) = r;
            }
        }
        __syncthreads();

        {   // Layer 2
            float acc[4][4];
#pragma unroll
            for (int si = 0; si < 4; ++si)
#pragma unroll
                for (int oj = 0; oj < 4; ++oj) acc[si][oj] = 0.0f;
            const float4* a0 = (const float4*)(bufB + (sg     ) * BUFW);
            const float4* a1 = (const float4*)(bufB + (sg + 16) * BUFW);
            const float4* a2 = (const float4*)(bufB + (sg + 32) * BUFW);
            const float4* a3 = (const float4*)(bufB + (sg + 48) * BUFW);
#pragma unroll
            for (int kk = 0; kk < 16; ++kk) {
                float4 v0 = a0[kk], v1 = a1[kk], v2 = a2[kk], v3 = a3[kk];
                float va0[4] = {v0.x, v0.y, v0.z, v0.w};
                float va1[4] = {v1.x, v1.y, v1.z, v1.w};
                float va2[4] = {v2.x, v2.y, v2.z, v2.w};
                float va3[4] = {v3.x, v3.y, v3.z, v3.w};
#pragma unroll
                for (int j = 0; j < 4; ++j) {
                    float4 w = *(const float4*)(W2s + (kk * 4 + j) * 64 + og * 4);
                    float wv[4] = {w.x, w.y, w.z, w.w};
#pragma unroll
                    for (int oj = 0; oj < 4; ++oj) {
                        acc[0][oj] = fmaf(va0[j], wv[oj], acc[0][oj]);
                        acc[1][oj] = fmaf(va1[j], wv[oj], acc[1][oj]);
                        acc[2][oj] = fmaf(va2[j], wv[oj], acc[2][oj]);
                        acc[3][oj] = fmaf(va3[j], wv[oj], acc[3][oj]);
                    }
                }
            }
#pragma unroll
            for (int si = 0; si < 4; ++si) {
                float4 r;
                int o0 = og * 4;
                r.x = fmaxf(fmaf(acc[si][0], sv[128 + o0],     sv[192 + o0]),     0.0f);
                r.y = fmaxf(fmaf(acc[si][1], sv[128 + o0 + 1], sv[192 + o0 + 1]), 0.0f);
                r.z = fmaxf(fmaf(acc[si][2], sv[128 + o0 + 2], sv[192 + o0 + 2]), 0.0f);
                r.w = fmaxf(fmaf(acc[si][3], sv[128 + o0 + 3], sv[192 + o0 + 3]), 0.0f);
                *(float4*)(bufA + (sg + 16 * si) * BUFW + o0) = r;
            }
        }
        __syncthreads();

        {   // Layer 3 + fused maxpool
            float acc[4][8];
#pragma unroll
            for (int si = 0; si < 4; ++si)
#pragma unroll
                for (int oj = 0; oj < 8; ++oj) acc[si][oj] = 0.0f;
            const float4* a0 = (const float4*)(bufA + (sg     ) * BUFW);
            const float4* a1 = (const float4*)(bufA + (sg + 16) * BUFW);
            const float4* a2 = (const float4*)(bufA + (sg + 32) * BUFW);
            const float4* a3 = (const float4*)(bufA + (sg + 48) * BUFW);
            const int o0 = og * 8;
#pragma unroll
            for (int kk = 0; kk < 16; ++kk) {
                float4 v0 = a0[kk], v1 = a1[kk], v2 = a2[kk], v3 = a3[kk];
                float va0[4] = {v0.x, v0.y, v0.z, v0.w};
                float va1[4] = {v1.x, v1.y, v1.z, v1.w};
                float va2[4] = {v2.x, v2.y, v2.z, v2.w};
                float va3[4] = {v3.x, v3.y, v3.z, v3.w};
#pragma unroll
                for (int j = 0; j < 4; ++j) {
                    float4 wA = *(const float4*)(W3s + (kk * 4 + j) * 128 + o0);
                    float4 wB = *(const float4*)(W3s + (kk * 4 + j) * 128 + o0 + 4);
                    float wv[8] = {wA.x, wA.y, wA.z, wA.w, wB.x, wB.y, wB.z, wB.w};
#pragma unroll
                    for (int oj = 0; oj < 8; ++oj) {
                        acc[0][oj] = fmaf(va0[j], wv[oj], acc[0][oj]);
                        acc[1][oj] = fmaf(va1[j], wv[oj], acc[1][oj]);
                        acc[2][oj] = fmaf(va2[j], wv[oj], acc[2][oj]);
                        acc[3][oj] = fmaf(va3[j], wv[oj], acc[3][oj]);
                    }
                }
            }
#pragma unroll
            for (int oj = 0; oj < 8; ++oj) {
                int o = o0 + oj;
                float sc = sv[256 + o], bi = sv[384 + o];
                float y0 = fmaxf(fmaf(acc[0][oj], sc, bi), 0.0f);
                float y1 = fmaxf(fmaf(acc[1][oj], sc, bi), 0.0f);
                float y2 = fmaxf(fmaf(acc[2][oj], sc, bi), 0.0f);
                float y3 = fmaxf(fmaf(acc[3][oj], sc, bi), 0.0f);
                atomicMax(&pooled[o],       __float_as_int(fmaxf(y0, y1)));
                atomicMax(&pooled[128 + o], __float_as_int(fmaxf(y2, y3)));
            }
        }
        __syncthreads();

        {
            int c = t >> 7, o = t & 127;
            int cid = cid0 + c;
            int bb = cid >> 10, jj = cid & (NCTR - 1);
            out[12288 + ((size_t)bb * 128 + o) * NCTR + jj] = __int_as_float(pooled[t]);
        }
        __syncthreads();
    }
}

// ---------------------------------------------------------------------------
extern "C" void kernel_launch(void* const* d_in, const int* in_sizes, int n_in,
                              void* d_out, int out_size)
{
    const float* xyz      = (const float*)d_in[0];
    const float* features = (const float*)d_in[1];
    const float* W1 = (const float*)d_in[2];
    const float* s1 = (const float*)d_in[3];
    const float* b1 = (const float*)d_in[4];
    const float* W2 = (const float*)d_in[5];
    const float* s2 = (const float*)d_in[6];
    const float* b2 = (const float*)d_in[7];
    const float* W3 = (const float*)d_in[8];
    const float* s3 = (const float*)d_in[9];
    const float* b3 = (const float*)d_in[10];
    float* out = (float*)d_out;

    cudaFuncSetAttribute(fps_kernel, cudaFuncAttributeMaxDynamicSharedMemorySize,
                         FPS_SMEM);
    cudaFuncSetAttribute(mlp_kernel, cudaFuncAttributeMaxDynamicSharedMemorySize,
                         MLP_SMEM_BYTES);

    transpose_kernel<<<dim3(NPTS / 32, 2, NB), dim3(32, 8)>>>(features);
    fps_kernel<<<NB, 1024, FPS_SMEM>>>(xyz, out);
    ballquery_kernel<<<(NB * NCTR * 32) / 256, 256>>>(xyz, out);
    mlp_kernel<<<(NB * NCTR) / CPB, 256, MLP_SMEM_BYTES>>>(
        xyz, W1, s1, b1, W2, s2, b2, W3, s3, b3, out);
}

// round 7
// speedup vs baseline: 2.1827x; 1.0676x over previous
#include <cuda_runtime.h>
#include <cuda_bf16.h>
#include <stdint.h>

#define NB    4
#define NPTS  16384
#define NCTR  1024
#define NSAMP 32
#define R2    0.04f

// ---------------- scratch (no allocations allowed) ----------------
__device__ float g_featsT[(size_t)NB * NPTS * 64];   // (B,N,C)
__device__ int   g_ballidx[NB * NCTR * NSAMP];

// ---------------------------------------------------------------------------
// 1) transpose features (B,64,N) -> (B,N,64)
// ---------------------------------------------------------------------------
__global__ void transpose_kernel(const float* __restrict__ f)
{
    __shared__ float tile[32][33];
    int n0 = blockIdx.x * 32, c0 = blockIdx.y * 32, b = blockIdx.z;
    int tx = threadIdx.x, ty = threadIdx.y;
    const float* src = f + (size_t)b * 64 * NPTS;
#pragma unroll
    for (int r = 0; r < 32; r += 8)
        tile[ty + r][tx] = src[(size_t)(c0 + ty + r) * NPTS + n0 + tx];
    __syncthreads();
    float* dst = g_featsT + (size_t)b * NPTS * 64;
#pragma unroll
    for (int r = 0; r < 32; r += 8)
        dst[(size_t)(n0 + ty + r) * 64 + c0 + tx] = tile[tx][ty + r];
}

// ---------------------------------------------------------------------------
// 2) FPS: exact bbox pruning, ONE barrier per iteration.
//    1 CTA/batch, 1024 threads, 16 pts/thread, counting-sorted into 8x8x8
//    cells. Key = (dist_bits << 32) | (16383 - orig_idx): unique keys,
//    max-key == argmax with first-original-index tie-break.
//    Winner coords derived from key via perm[] (orig idx -> sorted pos),
//    so there is no second publication phase. Per-warp best keys live in
//    uniform registers; double-buffered smem slots wk[k&1][warp] avoid the
//    fast-writer/slow-reader race across iterations.
// ---------------------------------------------------------------------------
#define FPS_CTRL_OFF (3 * NPTS * 4 + NPTS * 2)          // bytes
#define FPS_SMEM     (FPS_CTRL_OFF + 2048)              // 231424 B

__global__ void __launch_bounds__(1024, 1)
fps_kernel(const float* __restrict__ xyz, float* __restrict__ out)
{
    extern __shared__ float sm[];
    float* shx = sm;
    float* shy = sm + NPTS;
    float* shz = sm + 2 * NPTS;
    uint16_t* sp16 = (uint16_t*)(sm + 3 * NPTS);   // sidx during init, perm in loop
    unsigned int* ctrl = (unsigned int*)((char*)sm + FPS_CTRL_OFF);  // 2048 B
    unsigned int* hist = ctrl;                                        // setup only
    unsigned long long* wk = (unsigned long long*)ctrl;               // [2][32] aliases hist

    const int tid = threadIdx.x;
    const int b = blockIdx.x;
    const float* xb = xyz + (size_t)b * NPTS * 3;
    float* outx = out + (size_t)b * NCTR * 3;

    // ---- counting sort into 8x8x8 cells ----
    if (tid < 512) hist[tid] = 0u;
    __syncthreads();
    for (int p = tid; p < NPTS; p += 1024) {
        float x = xb[3 * p], y = xb[3 * p + 1], z = xb[3 * p + 2];
        int cx = min(7, (int)(x * 8.0f));
        int cy = min(7, (int)(y * 8.0f));
        int cz = min(7, (int)(z * 8.0f));
        atomicAdd(&hist[(cx << 6) | (cy << 3) | cz], 1u);
    }
    __syncthreads();
    if (tid < 32) {                         // exclusive prefix over 512 bins
        unsigned v[16], s = 0;
#pragma unroll
        for (int i = 0; i < 16; i++) { v[i] = hist[tid * 16 + i]; s += v[i]; }
        unsigned run = s;
#pragma unroll
        for (int o = 1; o < 32; o <<= 1) {
            unsigned t2 = __shfl_up_sync(0xffffffffu, run, o);
            if (tid >= o) run += t2;
        }
        unsigned acc = run - s;
#pragma unroll
        for (int i = 0; i < 16; i++) { unsigned c = v[i]; hist[tid * 16 + i] = acc; acc += c; }
    }
    __syncthreads();
    for (int p = tid; p < NPTS; p += 1024) {
        float x = xb[3 * p], y = xb[3 * p + 1], z = xb[3 * p + 2];
        int cx = min(7, (int)(x * 8.0f));
        int cy = min(7, (int)(y * 8.0f));
        int cz = min(7, (int)(z * 8.0f));
        unsigned pos = atomicAdd(&hist[(cx << 6) | (cy << 3) | cz], 1u);
        shx[pos] = x; shy[pos] = y; shz[pos] = z; sp16[pos] = (uint16_t)p;
    }
    __syncthreads();

    // ---- per-thread state: bbox, dists, packed inverse indices ----
    float lox = 1e30f, loy = 1e30f, loz = 1e30f;
    float hix = -1e30f, hiy = -1e30f, hiz = -1e30f;
    float dist[16];
    unsigned origs[16];
    unsigned invp[8];                      // (16383 - orig_idx) as packed u16 pairs
#pragma unroll
    for (int j = 0; j < 16; j++) {
        float x = shx[tid * 16 + j], y = shy[tid * 16 + j], z = shz[tid * 16 + j];
        lox = fminf(lox, x); hix = fmaxf(hix, x);
        loy = fminf(loy, y); hiy = fmaxf(hiy, y);
        loz = fminf(loz, z); hiz = fmaxf(hiz, z);
        dist[j] = 10000000000.0f;
        origs[j] = (unsigned)sp16[tid * 16 + j];
        unsigned iv = 16383u - origs[j];
        if ((j & 1) == 0) invp[j >> 1] = iv;
        else              invp[j >> 1] |= iv << 16;
    }
    __syncthreads();
    // in-place inversion: sp16 becomes perm[orig] = sorted pos
#pragma unroll
    for (int j = 0; j < 16; j++) sp16[origs[j]] = (uint16_t)(tid * 16 + j);
    __syncthreads();

    unsigned myHi = 0x7f800000u, myLo = 0u;   // +inf => forced recompute on iter 0
    unsigned wbHi = 0u, wbLo = 0u;            // per-warp cached best (warp-uniform)

    float wx = xb[0], wy = xb[1], wz = xb[2]; // first center = point 0

    const float4* px4 = (const float4*)shx + tid * 4;
    const float4* py4 = (const float4*)shy + tid * 4;
    const float4* pz4 = (const float4*)shz + tid * 4;
    const int lane = tid & 31, w = tid >> 5;

    for (int k = 0; k < NCTR; k++) {
        if (tid == 0) {
            outx[3 * k] = wx; outx[3 * k + 1] = wy; outx[3 * k + 2] = wz;
        }
        if (k == NCTR - 1) break;

        // ---- exact prune test ----
        float lbx = fmaxf(0.0f, fmaxf(lox - wx, wx - hix));
        float lby = fmaxf(0.0f, fmaxf(loy - wy, wy - hiy));
        float lbz = fmaxf(0.0f, fmaxf(loz - wz, wz - hiz));
        float lb2 = lbx * lbx + lby * lby + lbz * lbz;
        bool re = !(lb2 * 0.99999f > __uint_as_float(myHi));

        if (re) {
            unsigned long long nk = 0;
#pragma unroll
            for (int q = 0; q < 4; q++) {
                float4 xv = px4[q], yv = py4[q], zv = pz4[q];
                float xs[4] = {xv.x, xv.y, xv.z, xv.w};
                float ys[4] = {yv.x, yv.y, yv.z, yv.w};
                float zs[4] = {zv.x, zv.y, zv.z, zv.w};
#pragma unroll
                for (int c = 0; c < 4; c++) {
                    const int j = q * 4 + c;
                    float dx = __fsub_rn(xs[c], wx);
                    float dy = __fsub_rn(ys[c], wy);
                    float dz = __fsub_rn(zs[c], wz);
                    float d = __fadd_rn(__fadd_rn(__fmul_rn(dx, dx), __fmul_rn(dy, dy)),
                                        __fmul_rn(dz, dz));
                    float nd = fminf(dist[j], d);
                    dist[j] = nd;
                    unsigned iv = (j & 1) ? (invp[j >> 1] >> 16)
                                          : (invp[j >> 1] & 0xffffu);
                    unsigned long long pk =
                        ((unsigned long long)__float_as_uint(nd) << 32) | iv;
                    if (pk > nk) nk = pk;
                }
            }
            myHi = (unsigned)(nk >> 32); myLo = (unsigned)nk;
        }

        // ---- warp-best update via redux (skipped if whole warp pruned) ----
        unsigned m = __ballot_sync(0xffffffffu, re);
        if (m) {
            unsigned wm = __reduce_max_sync(0xffffffffu, myHi);
            unsigned cand = (myHi == wm) ? myLo : 0u;
            unsigned im = __reduce_max_sync(0xffffffffu, cand);
            wbHi = wm; wbLo = im;
        }
        const int ph = k & 1;
        if (lane == 0)
            wk[ph * 32 + w] = ((unsigned long long)wbHi << 32) | wbLo;
        __syncthreads();

        // ---- every warp computes the global winner (no 2nd barrier) ----
        unsigned long long v = wk[ph * 32 + lane];
        unsigned vh = (unsigned)(v >> 32), vl = (unsigned)v;
        unsigned gh = __reduce_max_sync(0xffffffffu, vh);
        unsigned cand2 = (vh == gh) ? vl : 0u;
        unsigned gl = __reduce_max_sync(0xffffffffu, cand2);
        unsigned pos = (unsigned)sp16[16383u - gl];
        wx = shx[pos]; wy = shy[pos]; wz = shz[pos];
    }
}

// ---------------------------------------------------------------------------
// 3) ball query: 1 warp per center, ascending-index append with early exit.
// ---------------------------------------------------------------------------
__global__ void __launch_bounds__(256)
ballquery_kernel(const float* __restrict__ xyz, const float* __restrict__ out)
{
    int gw = (blockIdx.x * blockDim.x + threadIdx.x) >> 5;
    int lane = threadIdx.x & 31;
    if (gw >= NB * NCTR) return;
    int b = gw >> 10, j = gw & (NCTR - 1);

    const float* xb = xyz + (size_t)b * NPTS * 3;
    const float* cp = out + ((size_t)b * NCTR + j) * 3;
    float cx = cp[0], cy = cp[1], cz = cp[2];
    int* outi = g_ballidx + ((size_t)b * NCTR + j) * NSAMP;

    int cnt = 0, firstidx = 0;
    for (int c = 0; c < NPTS / 32 && cnt < NSAMP; ++c) {
        int p = c * 32 + lane;
        float x = xb[3 * p], y = xb[3 * p + 1], z = xb[3 * p + 2];
        float dx = __fsub_rn(cx, x), dy = __fsub_rn(cy, y), dz = __fsub_rn(cz, z);
        float d2 = __fadd_rn(__fadd_rn(__fmul_rn(dx, dx), __fmul_rn(dy, dy)),
                             __fmul_rn(dz, dz));
        bool in = d2 < R2;
        unsigned m = __ballot_sync(0xffffffffu, in);
        if (m) {
            if (cnt == 0) {
                int src = __ffs(m) - 1;
                firstidx = __shfl_sync(0xffffffffu, p, src);
            }
            int rank = cnt + __popc(m & ((1u << lane) - 1u));
            if (in && rank < NSAMP) outi[rank] = p;
            cnt += __popc(m);
        }
    }
    if (cnt < NSAMP && lane >= cnt) outi[lane] = firstidx;
}

// ---------------------------------------------------------------------------
// 4) gather + MLP(67->64->64->128) + maxpool, register-tiled GEMM.
// ---------------------------------------------------------------------------
#define CPB  8
#define BUFW 68
#define OW1   0
#define OW2   (OW1 + 68 * 64)
#define OW3   (OW2 + 64 * 64)
#define OSV   (OW3 + 64 * 128)
#define OBA   (OSV + 512)
#define OBB   (OBA + 64 * BUFW)
#define OPOOL (OBB + 64 * BUFW)
#define OSIDX (OPOOL + 256)
#define MLP_SMEM_BYTES ((OSIDX + 64) * 4)

__global__ void __launch_bounds__(256, 2)
mlp_kernel(const float* __restrict__ xyz,
           const float* __restrict__ W1, const float* __restrict__ s1, const float* __restrict__ b1,
           const float* __restrict__ W2, const float* __restrict__ s2, const float* __restrict__ b2,
           const float* __restrict__ W3, const float* __restrict__ s3, const float* __restrict__ b3,
           float* __restrict__ out)
{
    extern __shared__ float smem[];
    float* W1s = smem + OW1;
    float* W2s = smem + OW2;
    float* W3s = smem + OW3;
    float* sv  = smem + OSV;
    float* bufA = smem + OBA;
    float* bufB = smem + OBB;
    int* pooled = (int*)(smem + OPOOL);
    int* sidx   = (int*)(smem + OSIDX);

    const int t = threadIdx.x;

    for (int e = t; e < 68 * 64; e += 256) {
        int j = e >> 6, o = e & 63;
        float v = (j < 64) ? W1[o * 67 + 3 + j] : (j < 67 ? W1[o * 67 + (j - 64)] : 0.0f);
        W1s[j * 64 + o] = v;
    }
    for (int e = t; e < 64 * 64; e += 256) {
        int i = e >> 6, o = e & 63;
        W2s[i * 64 + o] = W2[o * 64 + i];
    }
    for (int e = t; e < 64 * 128; e += 256) {
        int i = e >> 7, o = e & 127;
        W3s[i * 128 + o] = W3[o * 64 + i];
    }
    if (t < 64) { sv[t] = s1[t]; sv[64 + t] = b1[t]; sv[128 + t] = s2[t]; sv[192 + t] = b2[t]; }
    if (t < 128) { sv[256 + t] = s3[t]; sv[384 + t] = b3[t]; }

    const int sg = t >> 4;
    const int og = t & 15;

    for (int ch = 0; ch < CPB / 2; ++ch) {
        const int cid0 = blockIdx.x * CPB + ch * 2;

        pooled[t] = 0;
        if (t < 64) sidx[t] = g_ballidx[(size_t)(cid0 + (t >> 5)) * NSAMP + (t & 31)];
        __syncthreads();

        {
            int s = t & 63, part = t >> 6;
            int cid = cid0 + (s >> 5);
            int bb = cid >> 10, jj = cid & (NCTR - 1);
            int pi = sidx[s];
            const float4* frow = (const float4*)(g_featsT + ((size_t)bb * NPTS + pi) * 64);
            float4* dst = (float4*)(bufA + s * BUFW);
#pragma unroll
            for (int f = 0; f < 4; ++f) dst[part * 4 + f] = frow[part * 4 + f];
            if (part == 0) {
                const float* cp = out + ((size_t)bb * NCTR + jj) * 3;
                const float* pr = xyz + ((size_t)bb * NPTS + pi) * 3;
                bufA[s * BUFW + 64] = pr[0] - cp[0];
                bufA[s * BUFW + 65] = pr[1] - cp[1];
                bufA[s * BUFW + 66] = pr[2] - cp[2];
                bufA[s * BUFW + 67] = 0.0f;
            }
        }
        __syncthreads();

        {   // Layer 1: K=68 padded
            float acc[4][4];
#pragma unroll
            for (int si = 0; si < 4; ++si)
#pragma unroll
                for (int oj = 0; oj < 4; ++oj) acc[si][oj] = 0.0f;
            const float4* a0 = (const float4*)(bufA + (sg     ) * BUFW);
            const float4* a1 = (const float4*)(bufA + (sg + 16) * BUFW);
            const float4* a2 = (const float4*)(bufA + (sg + 32) * BUFW);
            const float4* a3 = (const float4*)(bufA + (sg + 48) * BUFW);
#pragma unroll
            for (int kk = 0; kk < 17; ++kk) {
                float4 v0 = a0[kk], v1 = a1[kk], v2 = a2[kk], v3 = a3[kk];
                float va0[4] = {v0.x, v0.y, v0.z, v0.w};
                float va1[4] = {v1.x, v1.y, v1.z, v1.w};
                float va2[4] = {v2.x, v2.y, v2.z, v2.w};
                float va3[4] = {v3.x, v3.y, v3.z, v3.w};
#pragma unroll
                for (int j = 0; j < 4; ++j) {
                    float4 w = *(const float4*)(W1s + (kk * 4 + j) * 64 + og * 4);
                    float wv[4] = {w.x, w.y, w.z, w.w};
#pragma unroll
                    for (int oj = 0; oj < 4; ++oj) {
                        acc[0][oj] = fmaf(va0[j], wv[oj], acc[0][oj]);
                        acc[1][oj] = fmaf(va1[j], wv[oj], acc[1][oj]);
                        acc[2][oj] = fmaf(va2[j], wv[oj], acc[2][oj]);
                        acc[3][oj] = fmaf(va3[j], wv[oj], acc[3][oj]);
                    }
                }
            }
#pragma unroll
            for (int si = 0; si < 4; ++si) {
                float4 r;
                int o0 = og * 4;
                r.x = fmaxf(fmaf(acc[si][0], sv[o0],     sv[64 + o0]),     0.0f);
                r.y = fmaxf(fmaf(acc[si][1], sv[o0 + 1], sv[64 + o0 + 1]), 0.0f);
                r.z = fmaxf(fmaf(acc[si][2], sv[o0 + 2], sv[64 + o0 + 2]), 0.0f);
                r.w = fmaxf(fmaf(acc[si][3], sv[o0 + 3], sv[64 + o0 + 3]), 0.0f);
                *(float4*)(bufB + (sg + 16 * si) * BUFW + o0) = r;
            }
        }
        __syncthreads();

        {   // Layer 2
            float acc[4][4];
#pragma unroll
            for (int si = 0; si < 4; ++si)
#pragma unroll
                for (int oj = 0; oj < 4; ++oj) acc[si][oj] = 0.0f;
            const float4* a0 = (const float4*)(bufB + (sg     ) * BUFW);
            const float4* a1 = (const float4*)(bufB + (sg + 16) * BUFW);
            const float4* a2 = (const float4*)(bufB + (sg + 32) * BUFW);
            const float4* a3 = (const float4*)(bufB + (sg + 48) * BUFW);
#pragma unroll
            for (int kk = 0; kk < 16; ++kk) {
                float4 v0 = a0[kk], v1 = a1[kk], v2 = a2[kk], v3 = a3[kk];
                float va0[4] = {v0.x, v0.y, v0.z, v0.w};
                float va1[4] = {v1.x, v1.y, v1.z, v1.w};
                float va2[4] = {v2.x, v2.y, v2.z, v2.w};
                float va3[4] = {v3.x, v3.y, v3.z, v3.w};
#pragma unroll
                for (int j = 0; j < 4; ++j) {
                    float4 w = *(const float4*)(W2s + (kk * 4 + j) * 64 + og * 4);
                    float wv[4] = {w.x, w.y, w.z, w.w};
#pragma unroll
                    for (int oj = 0; oj < 4; ++oj) {
                        acc[0][oj] = fmaf(va0[j], wv[oj], acc[0][oj]);
                        acc[1][oj] = fmaf(va1[j], wv[oj], acc[1][oj]);
                        acc[2][oj] = fmaf(va2[j], wv[oj], acc[2][oj]);
                        acc[3][oj] = fmaf(va3[j], wv[oj], acc[3][oj]);
                    }
                }
            }
#pragma unroll
            for (int si = 0; si < 4; ++si) {
                float4 r;
                int o0 = og * 4;
                r.x = fmaxf(fmaf(acc[si][0], sv[128 + o0],     sv[192 + o0]),     0.0f);
                r.y = fmaxf(fmaf(acc[si][1], sv[128 + o0 + 1], sv[192 + o0 + 1]), 0.0f);
                r.z = fmaxf(fmaf(acc[si][2], sv[128 + o0 + 2], sv[192 + o0 + 2]), 0.0f);
                r.w = fmaxf(fmaf(acc[si][3], sv[128 + o0 + 3], sv[192 + o0 + 3]), 0.0f);
                *(float4*)(bufA + (sg + 16 * si) * BUFW + o0) = r;
            }
        }
        __syncthreads();

        {   // Layer 3 + fused maxpool
            float acc[4][8];
#pragma unroll
            for (int si = 0; si < 4; ++si)
#pragma unroll
                for (int oj = 0; oj < 8; ++oj) acc[si][oj] = 0.0f;
            const float4* a0 = (const float4*)(bufA + (sg     ) * BUFW);
            const float4* a1 = (const float4*)(bufA + (sg + 16) * BUFW);
            const float4* a2 = (const float4*)(bufA + (sg + 32) * BUFW);
            const float4* a3 = (const float4*)(bufA + (sg + 48) * BUFW);
            const int o0 = og * 8;
#pragma unroll
            for (int kk = 0; kk < 16; ++kk) {
                float4 v0 = a0[kk], v1 = a1[kk], v2 = a2[kk], v3 = a3[kk];
                float va0[4] = {v0.x, v0.y, v0.z, v0.w};
                float va1[4] = {v1.x, v1.y, v1.z, v1.w};
                float va2[4] = {v2.x, v2.y, v2.z, v2.w};
                float va3[4] = {v3.x, v3.y, v3.z, v3.w};
#pragma unroll
                for (int j = 0; j < 4; ++j) {
                    float4 wA = *(const float4*)(W3s + (kk * 4 + j) * 128 + o0);
                    float4 wB = *(const float4*)(W3s + (kk * 4 + j) * 128 + o0 + 4);
                    float wv[8] = {wA.x, wA.y, wA.z, wA.w, wB.x, wB.y, wB.z, wB.w};
#pragma unroll
                    for (int oj = 0; oj < 8; ++oj) {
                        acc[0][oj] = fmaf(va0[j], wv[oj], acc[0][oj]);
                        acc[1][oj] = fmaf(va1[j], wv[oj], acc[1][oj]);
                        acc[2][oj] = fmaf(va2[j], wv[oj], acc[2][oj]);
                        acc[3][oj] = fmaf(va3[j], wv[oj], acc[3][oj]);
                    }
                }
            }
#pragma unroll
            for (int oj = 0; oj < 8; ++oj) {
                int o = o0 + oj;
                float sc = sv[256 + o], bi = sv[384 + o];
                float y0 = fmaxf(fmaf(acc[0][oj], sc, bi), 0.0f);
                float y1 = fmaxf(fmaf(acc[1][oj], sc, bi), 0.0f);
                float y2 = fmaxf(fmaf(acc[2][oj], sc, bi), 0.0f);
                float y3 = fmaxf(fmaf(acc[3][oj], sc, bi), 0.0f);
                atomicMax(&pooled[o],       __float_as_int(fmaxf(y0, y1)));
                atomicMax(&pooled[128 + o], __float_as_int(fmaxf(y2, y3)));
            }
        }
        __syncthreads();

        {
            int c = t >> 7, o = t & 127;
            int cid = cid0 + c;
            int bb = cid >> 10, jj = cid & (NCTR - 1);
            out[12288 + ((size_t)bb * 128 + o) * NCTR + jj] = __int_as_float(pooled[t]);
        }
        __syncthreads();
    }
}

// ---------------------------------------------------------------------------
extern "C" void kernel_launch(void* const* d_in, const int* in_sizes, int n_in,
                              void* d_out, int out_size)
{
    const float* xyz      = (const float*)d_in[0];
    const float* features = (const float*)d_in[1];
    const float* W1 = (const float*)d_in[2];
    const float* s1 = (const float*)d_in[3];
    const float* b1 = (const float*)d_in[4];
    const float* W2 = (const float*)d_in[5];
    const float* s2 = (const float*)d_in[6];
    const float* b2 = (const float*)d_in[7];
    const float* W3 = (const float*)d_in[8];
    const float* s3 = (const float*)d_in[9];
    const float* b3 = (const float*)d_in[10];
    float* out = (float*)d_out;

    cudaFuncSetAttribute(fps_kernel, cudaFuncAttributeMaxDynamicSharedMemorySize,
                         FPS_SMEM);
    cudaFuncSetAttribute(mlp_kernel, cudaFuncAttributeMaxDynamicSharedMemorySize,
                         MLP_SMEM_BYTES);

    transpose_kernel<<<dim3(NPTS / 32, 2, NB), dim3(32, 8)>>>(features);
    fps_kernel<<<NB, 1024, FPS_SMEM>>>(xyz, out);
    ballquery_kernel<<<(NB * NCTR * 32) / 256, 256>>>(xyz, out);
    mlp_kernel<<<(NB * NCTR) / CPB, 256, MLP_SMEM_BYTES>>>(
        xyz, W1, s1, b1, W2, s2, b2, W3, s3, b3, out);
}

// round 8
// speedup vs baseline: 2.2832x; 1.0460x over previous
#include <cuda_runtime.h>
#include <cuda_bf16.h>
#include <stdint.h>

#define NB    4
#define NPTS  16384
#define NCTR  1024
#define NSAMP 32
#define R2    0.04f

// ---------------- scratch (no allocations allowed) ----------------
__device__ float g_featsT[(size_t)NB * NPTS * 64];   // (B,N,C)
__device__ int   g_ballidx[NB * NCTR * NSAMP];

// ---------------- packed f32x2 helpers (exact per-half RN) ----------------
__device__ __forceinline__ unsigned long long pack2(float lo, float hi) {
    unsigned long long r;
    asm("mov.b64 %0, {%1, %2};" : "=l"(r) : "f"(lo), "f"(hi));
    return r;
}
__device__ __forceinline__ void unpack2(unsigned long long v, float& lo, float& hi) {
    asm("mov.b64 {%0, %1}, %2;" : "=f"(lo), "=f"(hi) : "l"(v));
}
__device__ __forceinline__ unsigned long long add2(unsigned long long a, unsigned long long b) {
    unsigned long long r;
    asm("add.rn.f32x2 %0, %1, %2;" : "=l"(r) : "l"(a), "l"(b));
    return r;
}
__device__ __forceinline__ unsigned long long mul2(unsigned long long a, unsigned long long b) {
    unsigned long long r;
    asm("mul.rn.f32x2 %0, %1, %2;" : "=l"(r) : "l"(a), "l"(b));
    return r;
}

// ---------------------------------------------------------------------------
// 1) transpose features (B,64,N) -> (B,N,64)
// ---------------------------------------------------------------------------
__global__ void transpose_kernel(const float* __restrict__ f)
{
    __shared__ float tile[32][33];
    int n0 = blockIdx.x * 32, c0 = blockIdx.y * 32, b = blockIdx.z;
    int tx = threadIdx.x, ty = threadIdx.y;
    const float* src = f + (size_t)b * 64 * NPTS;
#pragma unroll
    for (int r = 0; r < 32; r += 8)
        tile[ty + r][tx] = src[(size_t)(c0 + ty + r) * NPTS + n0 + tx];
    __syncthreads();
    float* dst = g_featsT + (size_t)b * NPTS * 64;
#pragma unroll
    for (int r = 0; r < 32; r += 8)
        dst[(size_t)(n0 + ty + r) * 64 + c0 + tx] = tile[tx][ty + r];
}

// ---------------------------------------------------------------------------
// 2) FPS: exact bbox pruning, ONE barrier per iteration, f32x2 recompute.
//    1 CTA/batch, 1024 threads, 16 pts/thread, counting-sorted into 8x8x8
//    cells. Key = (dist_bits << 32) | (16383 - orig_idx): unique keys,
//    max-key == argmax with first-original-index tie-break.
//    Winner coords derived from key via perm[] (orig idx -> sorted pos).
//    Exactness: x + (-wx) == RN(x - wx); f32x2 halves are independent RN ops;
//    sum order (dx^2+dy^2)+dz^2 matches the reference.
// ---------------------------------------------------------------------------
#define FPS_CTRL_OFF (3 * NPTS * 4 + NPTS * 2)          // bytes
#define FPS_SMEM     (FPS_CTRL_OFF + 2048)              // 231424 B

__global__ void __launch_bounds__(1024, 1)
fps_kernel(const float* __restrict__ xyz, float* __restrict__ out)
{
    extern __shared__ float sm[];
    float* shx = sm;
    float* shy = sm + NPTS;
    float* shz = sm + 2 * NPTS;
    uint16_t* sp16 = (uint16_t*)(sm + 3 * NPTS);   // sidx during init, perm in loop
    unsigned int* ctrl = (unsigned int*)((char*)sm + FPS_CTRL_OFF);  // 2048 B
    unsigned int* hist = ctrl;                                        // setup only
    unsigned long long* wk = (unsigned long long*)ctrl;               // [2][32] aliases hist

    const int tid = threadIdx.x;
    const int b = blockIdx.x;
    const float* xb = xyz + (size_t)b * NPTS * 3;
    float* outx = out + (size_t)b * NCTR * 3;

    // ---- counting sort into 8x8x8 cells ----
    if (tid < 512) hist[tid] = 0u;
    __syncthreads();
    for (int p = tid; p < NPTS; p += 1024) {
        float x = xb[3 * p], y = xb[3 * p + 1], z = xb[3 * p + 2];
        int cx = min(7, (int)(x * 8.0f));
        int cy = min(7, (int)(y * 8.0f));
        int cz = min(7, (int)(z * 8.0f));
        atomicAdd(&hist[(cx << 6) | (cy << 3) | cz], 1u);
    }
    __syncthreads();
    if (tid < 32) {                         // exclusive prefix over 512 bins
        unsigned v[16], s = 0;
#pragma unroll
        for (int i = 0; i < 16; i++) { v[i] = hist[tid * 16 + i]; s += v[i]; }
        unsigned run = s;
#pragma unroll
        for (int o = 1; o < 32; o <<= 1) {
            unsigned t2 = __shfl_up_sync(0xffffffffu, run, o);
            if (tid >= o) run += t2;
        }
        unsigned acc = run - s;
#pragma unroll
        for (int i = 0; i < 16; i++) { unsigned c = v[i]; hist[tid * 16 + i] = acc; acc += c; }
    }
    __syncthreads();
    for (int p = tid; p < NPTS; p += 1024) {
        float x = xb[3 * p], y = xb[3 * p + 1], z = xb[3 * p + 2];
        int cx = min(7, (int)(x * 8.0f));
        int cy = min(7, (int)(y * 8.0f));
        int cz = min(7, (int)(z * 8.0f));
        unsigned pos = atomicAdd(&hist[(cx << 6) | (cy << 3) | cz], 1u);
        shx[pos] = x; shy[pos] = y; shz[pos] = z; sp16[pos] = (uint16_t)p;
    }
    __syncthreads();

    // ---- per-thread state: bbox, dists, packed inverse indices ----
    float lox = 1e30f, loy = 1e30f, loz = 1e30f;
    float hix = -1e30f, hiy = -1e30f, hiz = -1e30f;
    float dist[16];
    unsigned origs[16];
    unsigned invp[8];                      // (16383 - orig_idx) as packed u16 pairs
#pragma unroll
    for (int j = 0; j < 16; j++) {
        float x = shx[tid * 16 + j], y = shy[tid * 16 + j], z = shz[tid * 16 + j];
        lox = fminf(lox, x); hix = fmaxf(hix, x);
        loy = fminf(loy, y); hiy = fmaxf(hiy, y);
        loz = fminf(loz, z); hiz = fmaxf(hiz, z);
        dist[j] = 10000000000.0f;
        origs[j] = (unsigned)sp16[tid * 16 + j];
        unsigned iv = 16383u - origs[j];
        if ((j & 1) == 0) invp[j >> 1] = iv;
        else              invp[j >> 1] |= iv << 16;
    }
    __syncthreads();
    // in-place inversion: sp16 becomes perm[orig] = sorted pos
#pragma unroll
    for (int j = 0; j < 16; j++) sp16[origs[j]] = (uint16_t)(tid * 16 + j);
    __syncthreads();

    unsigned myHi = 0x7f800000u, myLo = 0u;   // +inf => forced recompute on iter 0
    unsigned wbHi = 0u, wbLo = 0u;            // per-warp cached best (warp-uniform)

    float wx = xb[0], wy = xb[1], wz = xb[2]; // first center = point 0

    const float4* px4 = (const float4*)shx + tid * 4;
    const float4* py4 = (const float4*)shy + tid * 4;
    const float4* pz4 = (const float4*)shz + tid * 4;
    const int lane = tid & 31, w = tid >> 5;

    for (int k = 0; k < NCTR; k++) {
        if (tid == 0) {
            outx[3 * k] = wx; outx[3 * k + 1] = wy; outx[3 * k + 2] = wz;
        }
        if (k == NCTR - 1) break;

        // ---- exact prune test ----
        float lbx = fmaxf(0.0f, fmaxf(lox - wx, wx - hix));
        float lby = fmaxf(0.0f, fmaxf(loy - wy, wy - hiy));
        float lbz = fmaxf(0.0f, fmaxf(loz - wz, wz - hiz));
        float lb2 = lbx * lbx + lby * lby + lbz * lbz;
        bool re = !(lb2 * 0.99999f > __uint_as_float(myHi));

        if (re) {
            unsigned long long nk = 0;
            const unsigned long long nwx2 = pack2(-wx, -wx);
            const unsigned long long nwy2 = pack2(-wy, -wy);
            const unsigned long long nwz2 = pack2(-wz, -wz);
#pragma unroll
            for (int q = 0; q < 4; q++) {
                float4 xv = px4[q], yv = py4[q], zv = pz4[q];
#pragma unroll
                for (int h = 0; h < 2; h++) {
                    unsigned long long xp = (h == 0) ? pack2(xv.x, xv.y) : pack2(xv.z, xv.w);
                    unsigned long long yp = (h == 0) ? pack2(yv.x, yv.y) : pack2(yv.z, yv.w);
                    unsigned long long zp = (h == 0) ? pack2(zv.x, zv.y) : pack2(zv.z, zv.w);
                    unsigned long long dx = add2(xp, nwx2);
                    unsigned long long dy = add2(yp, nwy2);
                    unsigned long long dz = add2(zp, nwz2);
                    unsigned long long dd =
                        add2(add2(mul2(dx, dx), mul2(dy, dy)), mul2(dz, dz));
                    float dlo, dhi;
                    unpack2(dd, dlo, dhi);
                    const int j = q * 4 + h * 2;
                    float nd0 = fminf(dist[j],     dlo);
                    float nd1 = fminf(dist[j + 1], dhi);
                    dist[j] = nd0; dist[j + 1] = nd1;
                    unsigned pr = invp[j >> 1];
                    unsigned long long pk0 =
                        ((unsigned long long)__float_as_uint(nd0) << 32) | (pr & 0xffffu);
                    unsigned long long pk1 =
                        ((unsigned long long)__float_as_uint(nd1) << 32) | (pr >> 16);
                    if (pk0 > nk) nk = pk0;
                    if (pk1 > nk) nk = pk1;
                }
            }
            myHi = (unsigned)(nk >> 32); myLo = (unsigned)nk;
        }

        // ---- warp-best update via redux (skipped if whole warp pruned) ----
        unsigned m = __ballot_sync(0xffffffffu, re);
        if (m) {
            unsigned wm = __reduce_max_sync(0xffffffffu, myHi);
            unsigned cand = (myHi == wm) ? myLo : 0u;
            unsigned im = __reduce_max_sync(0xffffffffu, cand);
            wbHi = wm; wbLo = im;
        }
        const int ph = k & 1;
        if (lane == 0)
            wk[ph * 32 + w] = ((unsigned long long)wbHi << 32) | wbLo;
        __syncthreads();

        // ---- every warp computes the global winner (no 2nd barrier) ----
        unsigned long long v = wk[ph * 32 + lane];
        unsigned vh = (unsigned)(v >> 32), vl = (unsigned)v;
        unsigned gh = __reduce_max_sync(0xffffffffu, vh);
        unsigned cand2 = (vh == gh) ? vl : 0u;
        unsigned gl = __reduce_max_sync(0xffffffffu, cand2);
        unsigned pos = (unsigned)sp16[16383u - gl];
        wx = shx[pos]; wy = shy[pos]; wz = shz[pos];
    }
}

// ---------------------------------------------------------------------------
// 3) ball query: 1 warp per center, ascending-index append with early exit.
// ---------------------------------------------------------------------------
__global__ void __launch_bounds__(256)
ballquery_kernel(const float* __restrict__ xyz, const float* __restrict__ out)
{
    int gw = (blockIdx.x * blockDim.x + threadIdx.x) >> 5;
    int lane = threadIdx.x & 31;
    if (gw >= NB * NCTR) return;
    int b = gw >> 10, j = gw & (NCTR - 1);

    const float* xb = xyz + (size_t)b * NPTS * 3;
    const float* cp = out + ((size_t)b * NCTR + j) * 3;
    float cx = cp[0], cy = cp[1], cz = cp[2];
    int* outi = g_ballidx + ((size_t)b * NCTR + j) * NSAMP;

    int cnt = 0, firstidx = 0;
    for (int c = 0; c < NPTS / 32 && cnt < NSAMP; ++c) {
        int p = c * 32 + lane;
        float x = xb[3 * p], y = xb[3 * p + 1], z = xb[3 * p + 2];
        float dx = __fsub_rn(cx, x), dy = __fsub_rn(cy, y), dz = __fsub_rn(cz, z);
        float d2 = __fadd_rn(__fadd_rn(__fmul_rn(dx, dx), __fmul_rn(dy, dy)),
                             __fmul_rn(dz, dz));
        bool in = d2 < R2;
        unsigned m = __ballot_sync(0xffffffffu, in);
        if (m) {
            if (cnt == 0) {
                int src = __ffs(m) - 1;
                firstidx = __shfl_sync(0xffffffffu, p, src);
            }
            int rank = cnt + __popc(m & ((1u << lane) - 1u));
            if (in && rank < NSAMP) outi[rank] = p;
            cnt += __popc(m);
        }
    }
    if (cnt < NSAMP && lane >= cnt) outi[lane] = firstidx;
}

// ---------------------------------------------------------------------------
// 4) gather + MLP(67->64->64->128) + maxpool, register-tiled GEMM.
// ---------------------------------------------------------------------------
#define CPB  8
#define BUFW 68
#define OW1   0
#define OW2   (OW1 + 68 * 64)
#define OW3   (OW2 + 64 * 64)
#define OSV   (OW3 + 64 * 128)
#define OBA   (OSV + 512)
#define OBB   (OBA + 64 * BUFW)
#define OPOOL (OBB + 64 * BUFW)
#define OSIDX (OPOOL + 256)
#define MLP_SMEM_BYTES ((OSIDX + 64) * 4)

__global__ void __launch_bounds__(256, 2)
mlp_kernel(const float* __restrict__ xyz,
           const float* __restrict__ W1, const float* __restrict__ s1, const float* __restrict__ b1,
           const float* __restrict__ W2, const float* __restrict__ s2, const float* __restrict__ b2,
           const float* __restrict__ W3, const float* __restrict__ s3, const float* __restrict__ b3,
           float* __restrict__ out)
{
    extern __shared__ float smem[];
    float* W1s = smem + OW1;
    float* W2s = smem + OW2;
    float* W3s = smem + OW3;
    float* sv  = smem + OSV;
    float* bufA = smem + OBA;
    float* bufB = smem + OBB;
    int* pooled = (int*)(smem + OPOOL);
    int* sidx   = (int*)(smem + OSIDX);

    const int t = threadIdx.x;

    for (int e = t; e < 68 * 64; e += 256) {
        int j = e >> 6, o = e & 63;
        float v = (j < 64) ? W1[o * 67 + 3 + j] : (j < 67 ? W1[o * 67 + (j - 64)] : 0.0f);
        W1s[j * 64 + o] = v;
    }
    for (int e = t; e < 64 * 64; e += 256) {
        int i = e >> 6, o = e & 63;
        W2s[i * 64 + o] = W2[o * 64 + i];
    }
    for (int e = t; e < 64 * 128; e += 256) {
        int i = e >> 7, o = e & 127;
        W3s[i * 128 + o] = W3[o * 64 + i];
    }
    if (t < 64) { sv[t] = s1[t]; sv[64 + t] = b1[t]; sv[128 + t] = s2[t]; sv[192 + t] = b2[t]; }
    if (t < 128) { sv[256 + t] = s3[t]; sv[384 + t] = b3[t]; }

    const int sg = t >> 4;
    const int og = t & 15;

    for (int ch = 0; ch < CPB / 2; ++ch) {
        const int cid0 = blockIdx.x * CPB + ch * 2;

        pooled[t] = 0;
        if (t < 64) sidx[t] = g_ballidx[(size_t)(cid0 + (t >> 5)) * NSAMP + (t & 31)];
        __syncthreads();

        {
            int s = t & 63, part = t >> 6;
            int cid = cid0 + (s >> 5);
            int bb = cid >> 10, jj = cid & (NCTR - 1);
            int pi = sidx[s];
            const float4* frow = (const float4*)(g_featsT + ((size_t)bb * NPTS + pi) * 64);
            float4* dst = (float4*)(bufA + s * BUFW);
#pragma unroll
            for (int f = 0; f < 4; ++f) dst[part * 4 + f] = frow[part * 4 + f];
            if (part == 0) {
                const float* cp = out + ((size_t)bb * NCTR + jj) * 3;
                const float* pr = xyz + ((size_t)bb * NPTS + pi) * 3;
                bufA[s * BUFW + 64] = pr[0] - cp[0];
                bufA[s * BUFW + 65] = pr[1] - cp[1];
                bufA[s * BUFW + 66] = pr[2] - cp[2];
                bufA[s * BUFW + 67] = 0.0f;
            }
        }
        __syncthreads();

        {   // Layer 1: K=68 padded
            float acc[4][4];
#pragma unroll
            for (int si = 0; si < 4; ++si)
#pragma unroll
                for (int oj = 0; oj < 4; ++oj) acc[si][oj] = 0.0f;
            const float4* a0 = (const float4*)(bufA + (sg     ) * BUFW);
            const float4* a1 = (const float4*)(bufA + (sg + 16) * BUFW);
            const float4* a2 = (const float4*)(bufA + (sg + 32) * BUFW);
            const float4* a3 = (const float4*)(bufA + (sg + 48) * BUFW);
#pragma unroll
            for (int kk = 0; kk < 17; ++kk) {
                float4 v0 = a0[kk], v1 = a1[kk], v2 = a2[kk], v3 = a3[kk];
                float va0[4] = {v0.x, v0.y, v0.z, v0.w};
                float va1[4] = {v1.x, v1.y, v1.z, v1.w};
                float va2[4] = {v2.x, v2.y, v2.z, v2.w};
                float va3[4] = {v3.x, v3.y, v3.z, v3.w};
#pragma unroll
                for (int j = 0; j < 4; ++j) {
                    float4 w = *(const float4*)(W1s + (kk * 4 + j) * 64 + og * 4);
                    float wv[4] = {w.x, w.y, w.z, w.w};
#pragma unroll
                    for (int oj = 0; oj < 4; ++oj) {
                        acc[0][oj] = fmaf(va0[j], wv[oj], acc[0][oj]);
                        acc[1][oj] = fmaf(va1[j], wv[oj], acc[1][oj]);
                        acc[2][oj] = fmaf(va2[j], wv[oj], acc[2][oj]);
                        acc[3][oj] = fmaf(va3[j], wv[oj], acc[3][oj]);
                    }
                }
            }
#pragma unroll
            for (int si = 0; si < 4; ++si) {
                float4 r;
                int o0 = og * 4;
                r.x = fmaxf(fmaf(acc[si][0], sv[o0],     sv[64 + o0]),     0.0f);
                r.y = fmaxf(fmaf(acc[si][1], sv[o0 + 1], sv[64 + o0 + 1]), 0.0f);
                r.z = fmaxf(fmaf(acc[si][2], sv[o0 + 2], sv[64 + o0 + 2]), 0.0f);
                r.w = fmaxf(fmaf(acc[si][3], sv[o0 + 3], sv[64 + o0 + 3]), 0.0f);
                *(float4*)(bufB + (sg + 16 * si) * BUFW + o0) = r;
            }
        }
        __syncthreads();

        {   // Layer 2
            float acc[4][4];
#pragma unroll
            for (int si = 0; si < 4; ++si)
#pragma unroll
                for (int oj = 0; oj < 4; ++oj) acc[si][oj] = 0.0f;
            const float4* a0 = (const float4*)(bufB + (sg     ) * BUFW);
            const float4* a1 = (const float4*)(bufB + (sg + 16) * BUFW);
            const float4* a2 = (const float4*)(bufB + (sg + 32) * BUFW);
            const float4* a3 = (const float4*)(bufB + (sg + 48) * BUFW);
#pragma unroll
            for (int kk = 0; kk < 16; ++kk) {
                float4 v0 = a0[kk], v1 = a1[kk], v2 = a2[kk], v3 = a3[kk];
                float va0[4] = {v0.x, v0.y, v0.z, v0.w};
                float va1[4] = {v1.x, v1.y, v1.z, v1.w};
                float va2[4] = {v2.x, v2.y, v2.z, v2.w};
                float va3[4] = {v3.x, v3.y, v3.z, v3.w};
#pragma unroll
                for (int j = 0; j < 4; ++j) {
                    float4 w = *(const float4*)(W2s + (kk * 4 + j) * 64 + og * 4);
                    float wv[4] = {w.x, w.y, w.z, w.w};
#pragma unroll
                    for (int oj = 0; oj < 4; ++oj) {
                        acc[0][oj] = fmaf(va0[j], wv[oj], acc[0][oj]);
                        acc[1][oj] = fmaf(va1[j], wv[oj], acc[1][oj]);
                        acc[2][oj] = fmaf(va2[j], wv[oj], acc[2][oj]);
                        acc[3][oj] = fmaf(va3[j], wv[oj], acc[3][oj]);
                    }
                }
            }
#pragma unroll
            for (int si = 0; si < 4; ++si) {
                float4 r;
                int o0 = og * 4;
                r.x = fmaxf(fmaf(acc[si][0], sv[128 + o0],     sv[192 + o0]),     0.0f);
                r.y = fmaxf(fmaf(acc[si][1], sv[128 + o0 + 1], sv[192 + o0 + 1]), 0.0f);
                r.z = fmaxf(fmaf(acc[si][2], sv[128 + o0 + 2], sv[192 + o0 + 2]), 0.0f);
                r.w = fmaxf(fmaf(acc[si][3], sv[128 + o0 + 3], sv[192 + o0 + 3]), 0.0f);
                *(float4*)(bufA + (sg + 16 * si) * BUFW + o0) = r;
            }
        }
        __syncthreads();

        {   // Layer 3 + fused maxpool
            float acc[4][8];
#pragma unroll
            for (int si = 0; si < 4; ++si)
#pragma unroll
                for (int oj = 0; oj < 8; ++oj) acc[si][oj] = 0.0f;
            const float4* a0 = (const float4*)(bufA + (sg     ) * BUFW);
            const float4* a1 = (const float4*)(bufA + (sg + 16) * BUFW);
            const float4* a2 = (const float4*)(bufA + (sg + 32) * BUFW);
            const float4* a3 = (const float4*)(bufA + (sg + 48) * BUFW);
            const int o0 = og * 8;
#pragma unroll
            for (int kk = 0; kk < 16; ++kk) {
                float4 v0 = a0[kk], v1 = a1[kk], v2 = a2[kk], v3 = a3[kk];
                float va0[4] = {v0.x, v0.y, v0.z, v0.w};
                float va1[4] = {v1.x, v1.y, v1.z, v1.w};
                float va2[4] = {v2.x, v2.y, v2.z, v2.w};
                float va3[4] = {v3.x, v3.y, v3.z, v3.w};
#pragma unroll
                for (int j = 0; j < 4; ++j) {
                    float4 wA = *(const float4*)(W3s + (kk * 4 + j) * 128 + o0);
                    float4 wB = *(const float4*)(W3s + (kk * 4 + j) * 128 + o0 + 4);
                    float wv[8] = {wA.x, wA.y, wA.z, wA.w, wB.x, wB.y, wB.z, wB.w};
#pragma unroll
                    for (int oj = 0; oj < 8; ++oj) {
                        acc[0][oj] = fmaf(va0[j], wv[oj], acc[0][oj]);
                        acc[1][oj] = fmaf(va1[j], wv[oj], acc[1][oj]);
                        acc[2][oj] = fmaf(va2[j], wv[oj], acc[2][oj]);
                        acc[3][oj] = fmaf(va3[j], wv[oj], acc[3][oj]);
                    }
                }
            }
#pragma unroll
            for (int oj = 0; oj < 8; ++oj) {
                int o = o0 + oj;
                float sc = sv[256 + o], bi = sv[384 + o];
                float y0 = fmaxf(fmaf(acc[0][oj], sc, bi), 0.0f);
                float y1 = fmaxf(fmaf(acc[1][oj], sc, bi), 0.0f);
                float y2 = fmaxf(fmaf(acc[2][oj], sc, bi), 0.0f);
                float y3 = fmaxf(fmaf(acc[3][oj], sc, bi), 0.0f);
                atomicMax(&pooled[o],       __float_as_int(fmaxf(y0, y1)));
                atomicMax(&pooled[128 + o], __float_as_int(fmaxf(y2, y3)));
            }
        }
        __syncthreads();

        {
            int c = t >> 7, o = t & 127;
            int cid = cid0 + c;
            int bb = cid >> 10, jj = cid & (NCTR - 1);
            out[12288 + ((size_t)bb * 128 + o) * NCTR + jj] = __int_as_float(pooled[t]);
        }
        __syncthreads();
    }
}

// ---------------------------------------------------------------------------
extern "C" void kernel_launch(void* const* d_in, const int* in_sizes, int n_in,
                              void* d_out, int out_size)
{
    const float* xyz      = (const float*)d_in[0];
    const float* features = (const float*)d_in[1];
    const float* W1 = (const float*)d_in[2];
    const float* s1 = (const float*)d_in[3];
    const float* b1 = (const float*)d_in[4];
    const float* W2 = (const float*)d_in[5];
    const float* s2 = (const float*)d_in[6];
    const float* b2 = (const float*)d_in[7];
    const float* W3 = (const float*)d_in[8];
    const float* s3 = (const float*)d_in[9];
    const float* b3 = (const float*)d_in[10];
    float* out = (float*)d_out;

    cudaFuncSetAttribute(fps_kernel, cudaFuncAttributeMaxDynamicSharedMemorySize,
                         FPS_SMEM);
    cudaFuncSetAttribute(mlp_kernel, cudaFuncAttributeMaxDynamicSharedMemorySize,
                         MLP_SMEM_BYTES);

    transpose_kernel<<<dim3(NPTS / 32, 2, NB), dim3(32, 8)>>>(features);
    fps_kernel<<<NB, 1024, FPS_SMEM>>>(xyz, out);
    ballquery_kernel<<<(NB * NCTR * 32) / 256, 256>>>(xyz, out);
    mlp_kernel<<<(NB * NCTR) / CPB, 256, MLP_SMEM_BYTES>>>(
        xyz, W1, s1, b1, W2, s2, b2, W3, s3, b3, out);
}